// round 14
// baseline (speedup 1.0000x reference)
#include <cuda_runtime.h>
#include <cuda_bf16.h>
#include <cuda_fp16.h>
#include <cstdint>
#include <cstddef>

#define NN 50000
#define EE 800000
#define DD 128
#define GG 4
#define BN_EPS 1e-5f

// ---------------- static scratch (no allocations allowed) ----------------
__device__ int   g_cnt[NN + 1];
__device__ int   g_rowptr[NN + 1];
__device__ int   g_cursor[NN];
__device__ int   g_bsum[128];
__device__ uint2 g_epack[EE];                  // (src_idx, norm_bits)
__device__ float g_dinv[NN];
__device__ __half g_xh[(size_t)NN * DD];       // x converted to fp16
__device__ __half g_xa[(size_t)NN * DD];       // P @ x (fp16, fp32-accumulated)
__device__ __half g_z1[(size_t)GG * NN * DD];
__device__ __half g_h2[(size_t)GG * NN * DD];
__device__ __half g_t2[(size_t)GG * NN * DD];
__device__ float g_mix[(size_t)NN * GG];
__device__ float g_s1[GG * DD];
__device__ float g_q1[GG * DD];
__device__ float g_s2[GG * DD];
__device__ float g_q2[GG * DD];
__device__ __nv_bfloat16 g_w1h[(size_t)GG * DD * DD];
__device__ __nv_bfloat16 g_w1l[(size_t)GG * DD * DD];
__device__ __nv_bfloat16 g_w2h[(size_t)GG * DD * DD];
__device__ __nv_bfloat16 g_w2l[(size_t)GG * DD * DD];

// ---------------- setup ----------------
__global__ void k_zero(int* cnt, float* s1, float* q1, float* s2, float* q2) {
    int i = blockIdx.x * blockDim.x + threadIdx.x;
    if (i <= NN) cnt[i] = 0;
    if (i < GG * DD) { s1[i] = 0.f; q1[i] = 0.f; s2[i] = 0.f; q2[i] = 0.f; }
}

// merged (range-keyed): x->fp16 | histogram | softmax(mix_embed) | split W1 | split W2
__global__ void k_hist_misc(const float* __restrict__ x, __half* __restrict__ xh,
                            const int* __restrict__ col, int* cnt,
                            const float* __restrict__ me, float* __restrict__ mix,
                            const float* __restrict__ W1, __nv_bfloat16* __restrict__ w1h, __nv_bfloat16* __restrict__ w1l,
                            const float* __restrict__ W2, __nv_bfloat16* __restrict__ w2h, __nv_bfloat16* __restrict__ w2l) {
    int i = blockIdx.x * blockDim.x + threadIdx.x;
    // range 0: x -> fp16, vectorized 4 elems/thread
    if (i < NN * DD / 4) {
        float4 f = ((const float4*)x)[i];
        __half2 a = __floats2half2_rn(f.x, f.y);
        __half2 b = __floats2half2_rn(f.z, f.w);
        uint2 o; o.x = *(uint32_t*)&a; o.y = *(uint32_t*)&b;
        ((uint2*)xh)[i] = o;
        return;
    }
    int e = i - NN * DD / 4;
    if (e < EE) {
        int c = col[e];
        if ((unsigned)c < (unsigned)NN) atomicAdd(&cnt[c], 1);
        return;
    }
    int m = e - EE;
    if (m < NN) {
        float m0 = me[m*4+0], m1 = me[m*4+1], m2 = me[m*4+2], m3 = me[m*4+3];
        float mx = fmaxf(fmaxf(m0, m1), fmaxf(m2, m3));
        float e0 = expf(m0-mx), e1 = expf(m1-mx), e2 = expf(m2-mx), e3 = expf(m3-mx);
        float inv = 1.0f / (e0 + e1 + e2 + e3);
        mix[m*4+0] = e0*inv; mix[m*4+1] = e1*inv; mix[m*4+2] = e2*inv; mix[m*4+3] = e3*inv;
        return;
    }
    int j = m - NN;
    const float* W;
    __nv_bfloat16 *Wh, *Wl;
    if (j < GG * DD * DD) { W = W1; Wh = w1h; Wl = w1l; }
    else {
        j -= GG * DD * DD;
        if (j >= GG * DD * DD) return;
        W = W2; Wh = w2h; Wl = w2l;
    }
    int g = j >> 14, rem = j & 16383, n = rem >> 7, k = rem & 127;
    float w = W[(g << 14) + (k << 7) + n];          // transpose to [g][n][k]
    __nv_bfloat16 h = __float2bfloat16(w);
    Wh[j] = h;
    Wl[j] = __float2bfloat16(w - __bfloat162float(h));
}

__global__ void k_scan1(const int* __restrict__ cnt, int* __restrict__ rowptr,
                        int* __restrict__ bsum, float* __restrict__ dinv) {
    __shared__ int s[512];
    int tid = threadIdx.x;
    int i = blockIdx.x * 512 + tid;
    int v = (i <= NN) ? cnt[i] : 0;
    if (i < NN) dinv[i] = rsqrtf((float)v + 1.0f);   // +1 self-loop
    s[tid] = v;
    __syncthreads();
    #pragma unroll
    for (int off = 1; off < 512; off <<= 1) {
        int t = (tid >= off) ? s[tid - off] : 0;
        __syncthreads();
        s[tid] += t;
        __syncthreads();
    }
    if (i <= NN) rowptr[i] = s[tid] - v;
    if (tid == 511) bsum[blockIdx.x] = s[511];
}
__global__ void k_scan3(int* __restrict__ rowptr, const int* __restrict__ bsum,
                        int* __restrict__ cursor, int nb) {
    __shared__ int s[128];
    int tid = threadIdx.x;
    if (tid < 128) {
        int v = (tid < nb) ? bsum[tid] : 0;
        s[tid] = v;
    }
    __syncthreads();
    if (tid < 128) {
        #pragma unroll
        for (int off = 1; off < 128; off <<= 1) {
            int t = (tid >= off) ? s[tid - off] : 0;
            __syncthreads();
            s[tid] += t;
            __syncthreads();
        }
    } else {
        #pragma unroll
        for (int off = 1; off < 128; off <<= 1) { __syncthreads(); __syncthreads(); }
    }
    int boff = s[blockIdx.x] - bsum[blockIdx.x];
    int i = blockIdx.x * 512 + tid;
    if (i <= NN) {
        int r = rowptr[i] + boff;
        rowptr[i] = r;
        if (i < NN) cursor[i] = r;
    }
}
__global__ void k_place(const int* __restrict__ row, const int* __restrict__ col,
                        const float* __restrict__ dinv,
                        int* __restrict__ cursor, uint2* __restrict__ epack) {
    int e = blockIdx.x * blockDim.x + threadIdx.x;
    if (e >= EE) return;
    int r = row[e], c = col[e];
    if ((unsigned)r >= (unsigned)NN || (unsigned)c >= (unsigned)NN) return;
    int pos = atomicAdd(&cursor[c], 1);
    uint2 pk;
    pk.x = (unsigned)r;
    pk.y = __float_as_uint(dinv[r] * dinv[c]);
    epack[pos] = pk;
}

// ---------------- gather fp16 src/dst, fp32 accumulate, optional fused BN stats ----------------
__device__ __forceinline__ float4 h2f4(uint2 r) {
    __half2 a = *(__half2*)&r.x, b = *(__half2*)&r.y;
    float2 fa = __half22float2(a), fb = __half22float2(b);
    return make_float4(fa.x, fa.y, fb.x, fb.y);
}
__device__ __forceinline__ uint2 f4h2(float4 v) {
    __half2 a = __floats2half2_rn(v.x, v.y);
    __half2 b = __floats2half2_rn(v.z, v.w);
    uint2 r;
    r.x = *(uint32_t*)&a; r.y = *(uint32_t*)&b;
    return r;
}

__global__ void __launch_bounds__(256) k_gather_h(
    const uint2* __restrict__ src, uint2* __restrict__ dst,
    const int* __restrict__ rowptr, const uint2* __restrict__ epack,
    const float* __restrict__ dinv,
    float* __restrict__ osum, float* __restrict__ osumsq)
{
    __shared__ float sbs[128], sbq[128];
    int gy = blockIdx.y;
    src += (size_t)gy * NN * 32;        // row = 32 uint2 (128 half)
    dst += (size_t)gy * NN * 32;
    int tid = threadIdx.x, wid = tid >> 5, lane = tid & 31;
    bool wantStats = (osum != nullptr);
    if (wantStats) {
        if (tid < 128) { sbs[tid] = 0.f; sbq[tid] = 0.f; }
        __syncthreads();
    }

    float s[4] = {0.f, 0.f, 0.f, 0.f}, q[4] = {0.f, 0.f, 0.f, 0.f};
    int n0 = blockIdx.x * 64 + wid * 8;
    for (int i = 0; i < 8; ++i) {
        int n = n0 + i;
        if (n >= NN) break;
        float dw = dinv[n];
        float w0 = dw * dw;
        float4 a = h2f4(src[(size_t)n * 32 + lane]);
        float4 acc = make_float4(a.x * w0, a.y * w0, a.z * w0, a.w * w0);
        int j0 = rowptr[n], j1 = rowptr[n + 1];
        int j = j0;
        for (; j + 8 <= j1; j += 8) {
            uint2 mt[8];
            #pragma unroll
            for (int t = 0; t < 8; ++t) mt[t] = epack[j+t];
            uint2 rv[8];
            #pragma unroll
            for (int t = 0; t < 8; ++t) rv[t] = src[(size_t)mt[t].x * 32 + lane];
            #pragma unroll
            for (int t = 0; t < 8; ++t) {
                float u = __uint_as_float(mt[t].y);
                float4 v = h2f4(rv[t]);
                acc.x += u*v.x; acc.y += u*v.y;
                acc.z += u*v.z; acc.w += u*v.w;
            }
        }
        for (; j + 4 <= j1; j += 4) {
            uint2 mt[4];
            #pragma unroll
            for (int t = 0; t < 4; ++t) mt[t] = epack[j+t];
            uint2 rv[4];
            #pragma unroll
            for (int t = 0; t < 4; ++t) rv[t] = src[(size_t)mt[t].x * 32 + lane];
            #pragma unroll
            for (int t = 0; t < 4; ++t) {
                float u = __uint_as_float(mt[t].y);
                float4 v = h2f4(rv[t]);
                acc.x += u*v.x; acc.y += u*v.y;
                acc.z += u*v.z; acc.w += u*v.w;
            }
        }
        for (; j < j1; ++j) {
            uint2 mt = epack[j];
            float w = __uint_as_float(mt.y);
            float4 v = h2f4(src[(size_t)mt.x * 32 + lane]);
            acc.x += w * v.x; acc.y += w * v.y; acc.z += w * v.z; acc.w += w * v.w;
        }
        dst[(size_t)n * 32 + lane] = f4h2(acc);
        if (wantStats) {
            s[0] += acc.x; q[0] += acc.x * acc.x;
            s[1] += acc.y; q[1] += acc.y * acc.y;
            s[2] += acc.z; q[2] += acc.z * acc.z;
            s[3] += acc.w; q[3] += acc.w * acc.w;
        }
    }
    if (wantStats) {
        int c = lane * 4;
        atomicAdd(&sbs[c + 0], s[0]); atomicAdd(&sbq[c + 0], q[0]);
        atomicAdd(&sbs[c + 1], s[1]); atomicAdd(&sbq[c + 1], q[1]);
        atomicAdd(&sbs[c + 2], s[2]); atomicAdd(&sbq[c + 2], q[2]);
        atomicAdd(&sbs[c + 3], s[3]); atomicAdd(&sbq[c + 3], q[3]);
        __syncthreads();
        if (tid < 128) {
            atomicAdd(&osum[gy * DD + tid], sbs[tid]);
            atomicAdd(&osumsq[gy * DD + tid], sbq[tid]);
        }
    }
}

// ---------------- GEMM: C = A @ W^T, mma.sync bf16 3-term split, fused BN in/out ----------------
#define TROW 272
#define SM_WH 0
#define SM_WL (SM_WH + 128 * TROW)
#define SM_AH (SM_WL + 128 * TROW)
#define SM_AL (SM_AH + 128 * TROW)
#define GT_SMEM (SM_AL + 128 * TROW)

__device__ __forceinline__ void mma_bf16(float* d, const uint32_t* a, const uint32_t* b) {
    asm volatile(
        "mma.sync.aligned.m16n8k16.row.col.f32.bf16.bf16.f32 "
        "{%0,%1,%2,%3}, {%4,%5,%6,%7}, {%8,%9}, {%0,%1,%2,%3};"
        : "+f"(d[0]), "+f"(d[1]), "+f"(d[2]), "+f"(d[3])
        : "r"(a[0]), "r"(a[1]), "r"(a[2]), "r"(a[3]), "r"(b[0]), "r"(b[1]));
}
__device__ __forceinline__ uint32_t pack_bf2(float x, float y) {
    __nv_bfloat162 t = __floats2bfloat162_rn(x, y);
    return *(uint32_t*)&t;
}

// A input: fp16 (Ah16). Output fp16 (Ch).
__global__ void __launch_bounds__(256) k_gemm_mma(
    const __half* __restrict__ Ah16,
    const __nv_bfloat16* __restrict__ Bh, const __nv_bfloat16* __restrict__ Bl,
    __half* __restrict__ Ch, int M,
    const float* __restrict__ bn_sum, const float* __restrict__ bn_sumsq,
    const float* __restrict__ gamma, const float* __restrict__ beta,
    const float* __restrict__ alpha_p, int applyBN,
    float* osum, float* osumsq, int wantStats, size_t aStride)
{
    extern __shared__ char sm[];
    __shared__ float sbs[128], sbq[128];
    int gy = blockIdx.y;
    Ah16 += (size_t)gy * aStride;
    Bh += (size_t)gy * (DD * DD);
    Bl += (size_t)gy * (DD * DD);
    Ch += (size_t)gy * NN * DD;
    if (applyBN) {
        bn_sum += gy * DD; bn_sumsq += gy * DD;
        gamma  += gy * DD; beta     += gy * DD;
    }
    int tid = threadIdx.x, wid = tid >> 5, lane = tid & 31;

    if (wantStats && tid < 128) { sbs[tid] = 0.f; sbq[tid] = 0.f; }

    {
        int n = tid >> 1;
        int k0 = (tid & 1) * 64;
        const uint4* bh = (const uint4*)(Bh + (size_t)n * 128 + k0);
        const uint4* bl = (const uint4*)(Bl + (size_t)n * 128 + k0);
        char* wh = sm + SM_WH + n * TROW + k0 * 2;
        char* wl = sm + SM_WL + n * TROW + k0 * 2;
        #pragma unroll
        for (int i = 0; i < 8; ++i) {
            *(uint4*)(wh + i * 16) = bh[i];
            *(uint4*)(wl + i * 16) = bl[i];
        }
    }
    {
        int r = tid >> 1;
        int k0 = (tid & 1) * 64;
        int gr = blockIdx.x * 128 + r;
        bool valid = gr < M;
        float alpha = applyBN ? *alpha_p : 0.f;
        const float invN = 1.0f / (float)NN;
        char* ah = sm + SM_AH + r * TROW + k0 * 2;
        char* al = sm + SM_AL + r * TROW + k0 * 2;
        #pragma unroll
        for (int i = 0; i < 16; ++i) {
            int k = k0 + i * 4;
            float v[4] = {0.f, 0.f, 0.f, 0.f};
            if (valid) {
                uint2 hv = *(const uint2*)(Ah16 + (size_t)gr * 128 + k);
                __half2* hh = (__half2*)&hv;
                float2 f0 = __half22float2(hh[0]), f1 = __half22float2(hh[1]);
                v[0] = f0.x; v[1] = f0.y; v[2] = f1.x; v[3] = f1.y;
            }
            if (applyBN) {
                #pragma unroll
                for (int j = 0; j < 4; ++j) {
                    int kk = k + j;
                    float mu  = bn_sum[kk] * invN;
                    float var = bn_sumsq[kk] * invN - mu * mu;
                    float rs  = rsqrtf(var + BN_EPS);
                    float z = (v[j] - mu) * rs * gamma[kk] + beta[kk];
                    v[j] = (z > 0.f) ? z : alpha * z;
                }
            }
            uint32_t h0 = pack_bf2(v[0], v[1]), h1 = pack_bf2(v[2], v[3]);
            float r0 = v[0] - __bfloat162float(__ushort_as_bfloat16((unsigned short)(h0 & 0xFFFF)));
            float r1 = v[1] - __bfloat162float(__ushort_as_bfloat16((unsigned short)(h0 >> 16)));
            float r2 = v[2] - __bfloat162float(__ushort_as_bfloat16((unsigned short)(h1 & 0xFFFF)));
            float r3 = v[3] - __bfloat162float(__ushort_as_bfloat16((unsigned short)(h1 >> 16)));
            uint32_t l0 = pack_bf2(r0, r1), l1 = pack_bf2(r2, r3);
            *(uint2*)(ah + i * 8) = make_uint2(h0, h1);
            *(uint2*)(al + i * 8) = make_uint2(l0, l1);
        }
    }
    __syncthreads();

    float acc[16][4];
    #pragma unroll
    for (int t = 0; t < 16; ++t)
        #pragma unroll
        for (int qq = 0; qq < 4; ++qq) acc[t][qq] = 0.f;

    int qrow = lane >> 2;
    int kb   = (lane & 3) * 4;

    #pragma unroll
    for (int kk = 0; kk < 8; ++kk) {
        int kbyte = kk * 32 + kb;
        const char* arow0  = sm + SM_AH + (wid * 16 + qrow) * TROW + kbyte;
        const char* arow0l = sm + SM_AL + (wid * 16 + qrow) * TROW + kbyte;
        uint32_t a_h[4], a_l[4];
        a_h[0] = *(const uint32_t*)(arow0);
        a_h[1] = *(const uint32_t*)(arow0 + 8 * TROW);
        a_h[2] = *(const uint32_t*)(arow0 + 16);
        a_h[3] = *(const uint32_t*)(arow0 + 8 * TROW + 16);
        a_l[0] = *(const uint32_t*)(arow0l);
        a_l[1] = *(const uint32_t*)(arow0l + 8 * TROW);
        a_l[2] = *(const uint32_t*)(arow0l + 16);
        a_l[3] = *(const uint32_t*)(arow0l + 8 * TROW + 16);
        #pragma unroll
        for (int nt = 0; nt < 16; ++nt) {
            const char* brow  = sm + SM_WH + (nt * 8 + qrow) * TROW + kbyte;
            const char* browl = sm + SM_WL + (nt * 8 + qrow) * TROW + kbyte;
            uint32_t b_h[2], b_l[2];
            b_h[0] = *(const uint32_t*)(brow);
            b_h[1] = *(const uint32_t*)(brow + 16);
            b_l[0] = *(const uint32_t*)(browl);
            b_l[1] = *(const uint32_t*)(browl + 16);
            mma_bf16(acc[nt], a_h, b_h);
            mma_bf16(acc[nt], a_h, b_l);
            mma_bf16(acc[nt], a_l, b_h);
        }
    }

    int row0 = blockIdx.x * 128 + wid * 16 + qrow;
    int row1 = row0 + 8;
    int colb = (lane & 3) * 2;
    #pragma unroll
    for (int nt = 0; nt < 16; ++nt) {
        int col = nt * 8 + colb;
        if (row0 < M) *(__half2*)(Ch + (size_t)row0 * 128 + col) = __floats2half2_rn(acc[nt][0], acc[nt][1]);
        if (row1 < M) *(__half2*)(Ch + (size_t)row1 * 128 + col) = __floats2half2_rn(acc[nt][2], acc[nt][3]);
    }
    if (wantStats) {
        #pragma unroll
        for (int nt = 0; nt < 16; ++nt) {
            float s0 = acc[nt][0] + acc[nt][2];
            float s1 = acc[nt][1] + acc[nt][3];
            float q0 = acc[nt][0]*acc[nt][0] + acc[nt][2]*acc[nt][2];
            float q1 = acc[nt][1]*acc[nt][1] + acc[nt][3]*acc[nt][3];
            #pragma unroll
            for (int o = 4; o < 32; o <<= 1) {
                s0 += __shfl_xor_sync(0xffffffffu, s0, o);
                s1 += __shfl_xor_sync(0xffffffffu, s1, o);
                q0 += __shfl_xor_sync(0xffffffffu, q0, o);
                q1 += __shfl_xor_sync(0xffffffffu, q1, o);
            }
            if (lane < 4) {
                int c0 = nt * 8 + lane * 2;
                atomicAdd(&sbs[c0],     s0); atomicAdd(&sbq[c0],     q0);
                atomicAdd(&sbs[c0 + 1], s1); atomicAdd(&sbq[c0 + 1], q1);
            }
        }
        __syncthreads();
        if (tid < 128) {
            atomicAdd(&osum[gy * DD + tid], sbs[tid]);
            atomicAdd(&osumsq[gy * DD + tid], sbq[tid]);
        }
    }
}

// ---------------- final: BN2 + PReLU + mixture over all G (fp16 t2, 2 elems/thread) ----------------
__global__ void k_final(const __half2* __restrict__ t2,
                        const float* __restrict__ s2, const float* __restrict__ q2,
                        const float* __restrict__ gamma2, const float* __restrict__ beta2,
                        const float* __restrict__ alpha_p,
                        const float* __restrict__ mix, float2* __restrict__ out) {
    int idx = blockIdx.x * blockDim.x + threadIdx.x;     // over NN*DD/2 half2
    if (idx >= NN * DD / 2) return;
    int n = idx >> 6;
    int c = (idx & 63) * 2;
    float a = *alpha_p;
    const float invN = 1.0f / (float)NN;
    float r0 = 0.f, r1 = 0.f;
    #pragma unroll
    for (int g = 0; g < GG; ++g) {
        float mu0  = s2[g * DD + c] * invN;
        float var0 = q2[g * DD + c] * invN - mu0 * mu0;
        float rs0  = rsqrtf(var0 + BN_EPS);
        float mu1  = s2[g * DD + c + 1] * invN;
        float var1 = q2[g * DD + c + 1] * invN - mu1 * mu1;
        float rs1  = rsqrtf(var1 + BN_EPS);
        float2 t = __half22float2(t2[(size_t)g * (NN * DD / 2) + idx]);
        float v0 = (t.x - mu0) * rs0 * gamma2[g * DD + c]     + beta2[g * DD + c];
        float v1 = (t.y - mu1) * rs1 * gamma2[g * DD + c + 1] + beta2[g * DD + c + 1];
        v0 = (v0 > 0.f) ? v0 : a * v0;
        v1 = (v1 > 0.f) ? v1 : a * v1;
        float m = mix[(size_t)n * GG + g];
        r0 += m * v0;
        r1 += m * v1;
    }
    out[idx] = make_float2(r0, r1);
}

// ---------------- launch ----------------
extern "C" void kernel_launch(void* const* d_in, const int* in_sizes, int n_in,
                              void* d_out, int out_size) {
    const float* x      = (const float*)d_in[0];
    const int*   ei     = (const int*)d_in[1];
    const float* W1     = (const float*)d_in[2];
    const float* W2     = (const float*)d_in[4];
    const float* gamma1 = (const float*)d_in[6];
    const float* beta1  = (const float*)d_in[7];
    const float* gamma2 = (const float*)d_in[8];
    const float* beta2  = (const float*)d_in[9];
    const float* alpha  = (const float*)d_in[10];
    const float* mixe   = (const float*)d_in[11];
    float*       out    = (float*)d_out;

    void* p;
    cudaGetSymbolAddress(&p, g_cnt);    int* cnt    = (int*)p;
    cudaGetSymbolAddress(&p, g_rowptr); int* rowptr = (int*)p;
    cudaGetSymbolAddress(&p, g_cursor); int* cursor = (int*)p;
    cudaGetSymbolAddress(&p, g_bsum);   int* bsum   = (int*)p;
    cudaGetSymbolAddress(&p, g_epack);  uint2* epack= (uint2*)p;
    cudaGetSymbolAddress(&p, g_dinv);   float* dinv = (float*)p;
    cudaGetSymbolAddress(&p, g_xh);     __half* xh  = (__half*)p;
    cudaGetSymbolAddress(&p, g_xa);     __half* xa  = (__half*)p;
    cudaGetSymbolAddress(&p, g_z1);     __half* z1  = (__half*)p;
    cudaGetSymbolAddress(&p, g_h2);     __half* h2  = (__half*)p;
    cudaGetSymbolAddress(&p, g_t2);     __half* t2  = (__half*)p;
    cudaGetSymbolAddress(&p, g_mix);    float* mix  = (float*)p;
    cudaGetSymbolAddress(&p, g_s1);     float* s1   = (float*)p;
    cudaGetSymbolAddress(&p, g_q1);     float* q1   = (float*)p;
    cudaGetSymbolAddress(&p, g_s2);     float* s2   = (float*)p;
    cudaGetSymbolAddress(&p, g_q2);     float* q2   = (float*)p;
    cudaGetSymbolAddress(&p, g_w1h);    __nv_bfloat16* w1h = (__nv_bfloat16*)p;
    cudaGetSymbolAddress(&p, g_w1l);    __nv_bfloat16* w1l = (__nv_bfloat16*)p;
    cudaGetSymbolAddress(&p, g_w2h);    __nv_bfloat16* w2h = (__nv_bfloat16*)p;
    cudaGetSymbolAddress(&p, g_w2l);    __nv_bfloat16* w2l = (__nv_bfloat16*)p;

    const int* row = ei;
    const int* col = ei + EE;

    const int T = 256;
    const int gN    = (NN + T) / T;
    const int gE    = (EE + T - 1) / T;
    const int gHM   = (NN * DD / 4 + EE + NN + 2 * GG * DD * DD + T - 1) / T;
    const int gFin  = (NN * DD / 2 + T - 1) / T;
    const int gRow  = (NN + 127) / 128;                    // 391
    const int nScan = (NN + 1 + 511) / 512;                // 98
    const int gGath = (NN + 63) / 64;                      // 782

    cudaFuncSetAttribute(k_gemm_mma, cudaFuncAttributeMaxDynamicSharedMemorySize, GT_SMEM);

    // setup: CSR + norm + x->fp16 + softmax + weight split (recomputed per call)
    k_zero<<<gN, T>>>(cnt, s1, q1, s2, q2);
    k_hist_misc<<<gHM, T>>>(x, xh, col, cnt, mixe, mix, W1, w1h, w1l, W2, w2h, w2l);
    k_scan1<<<nScan, 512>>>(cnt, rowptr, bsum, dinv);
    k_scan3<<<nScan, 512>>>(rowptr, bsum, cursor, nScan);
    k_place<<<gE, T>>>(row, col, dinv, cursor, epack);

    // shared layer-1 propagate: xa = P @ x (fp16 stream, fp32 accumulate, no stats)
    k_gather_h<<<dim3(gGath, 1), T>>>((const uint2*)xh, (uint2*)xa,
                                      rowptr, epack, dinv, nullptr, nullptr);

    // layer 1 (all G): z1[g] = xa @ W1[g]^T (fp16 in/out), fused stats (fp32) -> s1/q1
    k_gemm_mma<<<dim3(gRow, GG), T, GT_SMEM>>>(
        xa, w1h, w1l, z1, NN,
        nullptr, nullptr, nullptr, nullptr, nullptr, 0,
        s1, q1, 1, 0 /* shared A */);

    // layer 2 (all G): h2[g] = prelu(BN(z1[g])) @ W2[g]^T (fp16 in/out), BN fused in A-load
    k_gemm_mma<<<dim3(gRow, GG), T, GT_SMEM>>>(
        z1, w2h, w2l, h2, NN,
        s1, q1, gamma1, beta1, alpha, 1,
        nullptr, nullptr, 0, (size_t)NN * DD);

    // propagate (all G): t2[g] = P @ h2[g] (fp16 in/out, fp32 acc), fused stats -> s2/q2
    k_gather_h<<<dim3(gGath, GG), T>>>((const uint2*)h2, (uint2*)t2,
                                       rowptr, epack, dinv, s2, q2);

    // final: BN2 + PReLU + softmax-mix accumulate, single pass (fp16 t2)
    k_final<<<gFin, T>>>((const __half2*)t2, s2, q2, gamma2, beta2, alpha, mix, (float2*)out);
}

// round 15
// speedup vs baseline: 1.1016x; 1.1016x over previous
#include <cuda_runtime.h>
#include <cuda_bf16.h>
#include <cuda_fp16.h>
#include <cstdint>
#include <cstddef>

#define NN 50000
#define EE 800000
#define DD 128
#define GG 4
#define BN_EPS 1e-5f

// ---------------- static scratch (no allocations allowed) ----------------
__device__ int   g_cnt[NN + 1];
__device__ int   g_rowptr[NN + 1];
__device__ int   g_cursor[NN];
__device__ int   g_bsum[128];
__device__ int   g_esrc[EE];
__device__ float g_enorm[EE];
__device__ float g_dinv[NN];
__device__ float g_xa[(size_t)NN * DD];        // P @ x, fp32
__device__ __half g_z1[(size_t)GG * NN * DD];  // fp16 (BN1 stats stay fp32)
__device__ __half g_h2[(size_t)GG * NN * DD];  // fp16 edge-read stream
__device__ __half g_t2[(size_t)GG * NN * DD];  // fp16 (BN2 stats stay fp32)
__device__ float g_mix[(size_t)NN * GG];
__device__ float g_s1[GG * DD];
__device__ float g_q1[GG * DD];
__device__ float g_s2[GG * DD];
__device__ float g_q2[GG * DD];
__device__ __half g_w1h[(size_t)GG * DD * DD]; // fp16 weight hi
__device__ __half g_w1l[(size_t)GG * DD * DD]; // fp16 weight residual
__device__ __half g_w2h[(size_t)GG * DD * DD];
__device__ __half g_w2l[(size_t)GG * DD * DD];

// ---------------- setup ----------------
__global__ void k_zero(int* cnt, float* s1, float* q1, float* s2, float* q2) {
    int i = blockIdx.x * blockDim.x + threadIdx.x;
    if (i <= NN) cnt[i] = 0;
    if (i < GG * DD) { s1[i] = 0.f; q1[i] = 0.f; s2[i] = 0.f; q2[i] = 0.f; }
}

// merged: histogram | softmax(mix_embed) | split W1 | split W2  (range-keyed)
__global__ void k_hist_misc(const int* __restrict__ col, int* cnt,
                            const float* __restrict__ me, float* __restrict__ mix,
                            const float* __restrict__ W1, __half* __restrict__ w1h, __half* __restrict__ w1l,
                            const float* __restrict__ W2, __half* __restrict__ w2h, __half* __restrict__ w2l) {
    int i = blockIdx.x * blockDim.x + threadIdx.x;
    if (i < EE) {
        int c = col[i];
        if ((unsigned)c < (unsigned)NN) atomicAdd(&cnt[c], 1);
        return;
    }
    int m = i - EE;
    if (m < NN) {
        float m0 = me[m*4+0], m1 = me[m*4+1], m2 = me[m*4+2], m3 = me[m*4+3];
        float mx = fmaxf(fmaxf(m0, m1), fmaxf(m2, m3));
        float e0 = expf(m0-mx), e1 = expf(m1-mx), e2 = expf(m2-mx), e3 = expf(m3-mx);
        float inv = 1.0f / (e0 + e1 + e2 + e3);
        mix[m*4+0] = e0*inv; mix[m*4+1] = e1*inv; mix[m*4+2] = e2*inv; mix[m*4+3] = e3*inv;
        return;
    }
    int j = m - NN;
    const float* W;
    __half *Wh, *Wl;
    if (j < GG * DD * DD) { W = W1; Wh = w1h; Wl = w1l; }
    else {
        j -= GG * DD * DD;
        if (j >= GG * DD * DD) return;
        W = W2; Wh = w2h; Wl = w2l;
    }
    int g = j >> 14, rem = j & 16383, n = rem >> 7, k = rem & 127;
    float w = W[(g << 14) + (k << 7) + n];          // transpose to [g][n][k]
    __half h = __float2half_rn(w);
    Wh[j] = h;
    Wl[j] = __float2half_rn(w - __half2float(h));   // 22-bit effective precision
}

__global__ void k_scan1(const int* __restrict__ cnt, int* __restrict__ rowptr,
                        int* __restrict__ bsum, float* __restrict__ dinv) {
    __shared__ int s[512];
    int tid = threadIdx.x;
    int i = blockIdx.x * 512 + tid;
    int v = (i <= NN) ? cnt[i] : 0;
    if (i < NN) dinv[i] = rsqrtf((float)v + 1.0f);   // +1 self-loop
    s[tid] = v;
    __syncthreads();
    #pragma unroll
    for (int off = 1; off < 512; off <<= 1) {
        int t = (tid >= off) ? s[tid - off] : 0;
        __syncthreads();
        s[tid] += t;
        __syncthreads();
    }
    if (i <= NN) rowptr[i] = s[tid] - v;
    if (tid == 511) bsum[blockIdx.x] = s[511];
}
__global__ void k_scan3(int* __restrict__ rowptr, const int* __restrict__ bsum,
                        int* __restrict__ cursor, int nb) {
    __shared__ int s[128];
    int tid = threadIdx.x;
    if (tid < 128) {
        int v = (tid < nb) ? bsum[tid] : 0;
        s[tid] = v;
    }
    __syncthreads();
    if (tid < 128) {
        #pragma unroll
        for (int off = 1; off < 128; off <<= 1) {
            int t = (tid >= off) ? s[tid - off] : 0;
            __syncthreads();
            s[tid] += t;
            __syncthreads();
        }
    } else {
        #pragma unroll
        for (int off = 1; off < 128; off <<= 1) { __syncthreads(); __syncthreads(); }
    }
    int boff = s[blockIdx.x] - bsum[blockIdx.x];
    int i = blockIdx.x * 512 + tid;
    if (i <= NN) {
        int r = rowptr[i] + boff;
        rowptr[i] = r;
        if (i < NN) cursor[i] = r;
    }
}
__global__ void k_place(const int* __restrict__ row, const int* __restrict__ col,
                        const float* __restrict__ dinv,
                        int* __restrict__ cursor, int* __restrict__ esrc, float* __restrict__ enorm) {
    int e = blockIdx.x * blockDim.x + threadIdx.x;
    if (e >= EE) return;
    int r = row[e], c = col[e];
    if ((unsigned)r >= (unsigned)NN || (unsigned)c >= (unsigned)NN) return;
    int pos = atomicAdd(&cursor[c], 1);
    esrc[pos] = r;
    enorm[pos] = dinv[r] * dinv[c];
}

// ---------------- gather fp32 (xa = P @ x), edge loop unrolled x8 ----------------
__global__ void __launch_bounds__(256) k_gather(
    const float4* __restrict__ src, float4* __restrict__ dst,
    const int* __restrict__ rowptr, const int* __restrict__ esrc,
    const float* __restrict__ enorm, const float* __restrict__ dinv)
{
    int tid = threadIdx.x, wid = tid >> 5, lane = tid & 31;
    int n0 = blockIdx.x * 64 + wid * 8;
    for (int i = 0; i < 8; ++i) {
        int n = n0 + i;
        if (n >= NN) break;
        float dw = dinv[n];
        float w0 = dw * dw;
        float4 a = src[(size_t)n * 32 + lane];
        float4 acc = make_float4(a.x * w0, a.y * w0, a.z * w0, a.w * w0);
        int j0 = rowptr[n], j1 = rowptr[n + 1];
        int j = j0;
        for (; j + 8 <= j1; j += 8) {
            float4 v[8];
            float u[8];
            #pragma unroll
            for (int t = 0; t < 8; ++t) {
                v[t] = src[(size_t)esrc[j+t] * 32 + lane];
                u[t] = enorm[j+t];
            }
            #pragma unroll
            for (int t = 0; t < 8; ++t) {
                acc.x += u[t]*v[t].x; acc.y += u[t]*v[t].y;
                acc.z += u[t]*v[t].z; acc.w += u[t]*v[t].w;
            }
        }
        for (; j < j1; ++j) {
            int sn = esrc[j];
            float w = enorm[j];
            float4 v = src[(size_t)sn * 32 + lane];
            acc.x += w * v.x; acc.y += w * v.y; acc.z += w * v.z; acc.w += w * v.w;
        }
        dst[(size_t)n * 32 + lane] = acc;
    }
}

// ---------------- gather fp16 src/dst (t2 = P @ h2) + fused BN stats ----------------
__device__ __forceinline__ float4 h2f4(uint2 r) {
    __half2 a = *(__half2*)&r.x, b = *(__half2*)&r.y;
    float2 fa = __half22float2(a), fb = __half22float2(b);
    return make_float4(fa.x, fa.y, fb.x, fb.y);
}
__device__ __forceinline__ uint2 f4h2(float4 v) {
    __half2 a = __floats2half2_rn(v.x, v.y);
    __half2 b = __floats2half2_rn(v.z, v.w);
    uint2 r;
    r.x = *(uint32_t*)&a; r.y = *(uint32_t*)&b;
    return r;
}

__global__ void __launch_bounds__(256) k_gather_h(
    const uint2* __restrict__ src, uint2* __restrict__ dst,
    const int* __restrict__ rowptr, const int* __restrict__ esrc,
    const float* __restrict__ enorm, const float* __restrict__ dinv,
    float* __restrict__ osum, float* __restrict__ osumsq)
{
    __shared__ float sbs[128], sbq[128];
    int gy = blockIdx.y;
    src += (size_t)gy * NN * 32;        // row = 32 uint2 (128 half)
    dst += (size_t)gy * NN * 32;
    int tid = threadIdx.x, wid = tid >> 5, lane = tid & 31;
    if (tid < 128) { sbs[tid] = 0.f; sbq[tid] = 0.f; }
    __syncthreads();

    float s[4] = {0.f, 0.f, 0.f, 0.f}, q[4] = {0.f, 0.f, 0.f, 0.f};
    int n0 = blockIdx.x * 64 + wid * 8;
    for (int i = 0; i < 8; ++i) {
        int n = n0 + i;
        if (n >= NN) break;
        float dw = dinv[n];
        float w0 = dw * dw;
        float4 a = h2f4(src[(size_t)n * 32 + lane]);
        float4 acc = make_float4(a.x * w0, a.y * w0, a.z * w0, a.w * w0);
        int j0 = rowptr[n], j1 = rowptr[n + 1];
        int j = j0;
        for (; j + 8 <= j1; j += 8) {
            uint2 rv[8];
            float u[8];
            #pragma unroll
            for (int t = 0; t < 8; ++t) {
                rv[t] = src[(size_t)esrc[j+t] * 32 + lane];
                u[t]  = enorm[j+t];
            }
            #pragma unroll
            for (int t = 0; t < 8; ++t) {
                float4 v = h2f4(rv[t]);
                acc.x += u[t]*v.x; acc.y += u[t]*v.y;
                acc.z += u[t]*v.z; acc.w += u[t]*v.w;
            }
        }
        for (; j + 4 <= j1; j += 4) {
            uint2 rv[4];
            float u[4];
            #pragma unroll
            for (int t = 0; t < 4; ++t) {
                rv[t] = src[(size_t)esrc[j+t] * 32 + lane];
                u[t]  = enorm[j+t];
            }
            #pragma unroll
            for (int t = 0; t < 4; ++t) {
                float4 v = h2f4(rv[t]);
                acc.x += u[t]*v.x; acc.y += u[t]*v.y;
                acc.z += u[t]*v.z; acc.w += u[t]*v.w;
            }
        }
        for (; j < j1; ++j) {
            float w = enorm[j];
            float4 v = h2f4(src[(size_t)esrc[j] * 32 + lane]);
            acc.x += w * v.x; acc.y += w * v.y; acc.z += w * v.z; acc.w += w * v.w;
        }
        dst[(size_t)n * 32 + lane] = f4h2(acc);
        s[0] += acc.x; q[0] += acc.x * acc.x;
        s[1] += acc.y; q[1] += acc.y * acc.y;
        s[2] += acc.z; q[2] += acc.z * acc.z;
        s[3] += acc.w; q[3] += acc.w * acc.w;
    }
    int c = lane * 4;
    atomicAdd(&sbs[c + 0], s[0]); atomicAdd(&sbq[c + 0], q[0]);
    atomicAdd(&sbs[c + 1], s[1]); atomicAdd(&sbq[c + 1], q[1]);
    atomicAdd(&sbs[c + 2], s[2]); atomicAdd(&sbq[c + 2], q[2]);
    atomicAdd(&sbs[c + 3], s[3]); atomicAdd(&sbq[c + 3], q[3]);
    __syncthreads();
    if (tid < 128) {
        atomicAdd(&osum[gy * DD + tid], sbs[tid]);
        atomicAdd(&osumsq[gy * DD + tid], sbq[tid]);
    }
}

// ---------------- GEMM: C = A @ W^T, mma.sync fp16 2-term weight split ----------------
// smem: WH | WL | A, each 128 rows x 136 fp16 (272B row stride)
#define TROW 272
#define SM_WH 0
#define SM_WL (SM_WH + 128 * TROW)
#define SM_A  (SM_WL + 128 * TROW)
#define GT_SMEM (SM_A + 128 * TROW)

__device__ __forceinline__ void mma_f16(float* d, const uint32_t* a, const uint32_t* b) {
    asm volatile(
        "mma.sync.aligned.m16n8k16.row.col.f32.f16.f16.f32 "
        "{%0,%1,%2,%3}, {%4,%5,%6,%7}, {%8,%9}, {%0,%1,%2,%3};"
        : "+f"(d[0]), "+f"(d[1]), "+f"(d[2]), "+f"(d[3])
        : "r"(a[0]), "r"(a[1]), "r"(a[2]), "r"(a[3]), "r"(b[0]), "r"(b[1]));
}

// A input: fp32 (Af) or fp16 (Ah16) — exactly one non-null. A is fp16-rounded into smem.
// Output: fp16 (Ch).
__global__ void __launch_bounds__(256) k_gemm_mma(
    const float* __restrict__ Af, const __half* __restrict__ Ah16,
    const __half* __restrict__ Bh, const __half* __restrict__ Bl,
    __half* __restrict__ Ch, int M,
    const float* __restrict__ bn_sum, const float* __restrict__ bn_sumsq,
    const float* __restrict__ gamma, const float* __restrict__ beta,
    const float* __restrict__ alpha_p, int applyBN,
    float* osum, float* osumsq, int wantStats, size_t aStride)
{
    extern __shared__ char sm[];
    __shared__ float sbs[128], sbq[128];
    int gy = blockIdx.y;
    if (Af)   Af   += (size_t)gy * aStride;
    if (Ah16) Ah16 += (size_t)gy * aStride;
    Bh += (size_t)gy * (DD * DD);
    Bl += (size_t)gy * (DD * DD);
    Ch += (size_t)gy * NN * DD;
    if (applyBN) {
        bn_sum += gy * DD; bn_sumsq += gy * DD;
        gamma  += gy * DD; beta     += gy * DD;
    }
    int tid = threadIdx.x, wid = tid >> 5, lane = tid & 31;

    if (wantStats && tid < 128) { sbs[tid] = 0.f; sbq[tid] = 0.f; }

    // --- load W tiles (fp16 hi + residual, [n][k]) ---
    {
        int n = tid >> 1;
        int k0 = (tid & 1) * 64;
        const uint4* bh = (const uint4*)(Bh + (size_t)n * 128 + k0);
        const uint4* bl = (const uint4*)(Bl + (size_t)n * 128 + k0);
        char* wh = sm + SM_WH + n * TROW + k0 * 2;
        char* wl = sm + SM_WL + n * TROW + k0 * 2;
        #pragma unroll
        for (int i = 0; i < 8; ++i) {
            *(uint4*)(wh + i * 16) = bh[i];
            *(uint4*)(wl + i * 16) = bl[i];
        }
    }
    // --- load A rows, optional fused BN+PReLU, round to fp16 in smem ---
    {
        int r = tid >> 1;
        int k0 = (tid & 1) * 64;
        int gr = blockIdx.x * 128 + r;
        bool valid = gr < M;
        float alpha = applyBN ? *alpha_p : 0.f;
        const float invN = 1.0f / (float)NN;
        char* ap = sm + SM_A + r * TROW + k0 * 2;
        #pragma unroll
        for (int i = 0; i < 16; ++i) {
            int k = k0 + i * 4;
            float v[4] = {0.f, 0.f, 0.f, 0.f};
            if (valid) {
                if (Ah16) {
                    uint2 hv = *(const uint2*)(Ah16 + (size_t)gr * 128 + k);
                    __half2* hh = (__half2*)&hv;
                    float2 f0 = __half22float2(hh[0]), f1 = __half22float2(hh[1]);
                    v[0] = f0.x; v[1] = f0.y; v[2] = f1.x; v[3] = f1.y;
                } else {
                    float4 f = *(const float4*)(Af + (size_t)gr * 128 + k);
                    v[0] = f.x; v[1] = f.y; v[2] = f.z; v[3] = f.w;
                }
            }
            if (applyBN) {
                #pragma unroll
                for (int j = 0; j < 4; ++j) {
                    int kk = k + j;
                    float mu  = bn_sum[kk] * invN;
                    float var = bn_sumsq[kk] * invN - mu * mu;
                    float rs  = rsqrtf(var + BN_EPS);
                    float z = (v[j] - mu) * rs * gamma[kk] + beta[kk];
                    v[j] = (z > 0.f) ? z : alpha * z;
                }
            }
            __half2 p0 = __floats2half2_rn(v[0], v[1]);
            __half2 p1 = __floats2half2_rn(v[2], v[3]);
            *(uint2*)(ap + i * 8) = make_uint2(*(uint32_t*)&p0, *(uint32_t*)&p1);
        }
    }
    __syncthreads();

    // --- warp-level MMA: warp wid owns rows [wid*16, wid*16+16), 2 MMAs per (kk,nt) ---
    float acc[16][4];
    #pragma unroll
    for (int t = 0; t < 16; ++t)
        #pragma unroll
        for (int qq = 0; qq < 4; ++qq) acc[t][qq] = 0.f;

    int qrow = lane >> 2;
    int kb   = (lane & 3) * 4;

    #pragma unroll
    for (int kk = 0; kk < 8; ++kk) {
        int kbyte = kk * 32 + kb;
        const char* arow = sm + SM_A + (wid * 16 + qrow) * TROW + kbyte;
        uint32_t a_[4];
        a_[0] = *(const uint32_t*)(arow);
        a_[1] = *(const uint32_t*)(arow + 8 * TROW);
        a_[2] = *(const uint32_t*)(arow + 16);
        a_[3] = *(const uint32_t*)(arow + 8 * TROW + 16);
        #pragma unroll
        for (int nt = 0; nt < 16; ++nt) {
            const char* brow  = sm + SM_WH + (nt * 8 + qrow) * TROW + kbyte;
            const char* browl = sm + SM_WL + (nt * 8 + qrow) * TROW + kbyte;
            uint32_t b_h[2], b_l[2];
            b_h[0] = *(const uint32_t*)(brow);
            b_h[1] = *(const uint32_t*)(brow + 16);
            b_l[0] = *(const uint32_t*)(browl);
            b_l[1] = *(const uint32_t*)(browl + 16);
            mma_f16(acc[nt], a_, b_h);
            mma_f16(acc[nt], a_, b_l);
        }
    }

    // --- epilogue: store fp16 + optional fused BN stats ---
    int row0 = blockIdx.x * 128 + wid * 16 + qrow;
    int row1 = row0 + 8;
    int colb = (lane & 3) * 2;
    #pragma unroll
    for (int nt = 0; nt < 16; ++nt) {
        int col = nt * 8 + colb;
        if (row0 < M) *(__half2*)(Ch + (size_t)row0 * 128 + col) = __floats2half2_rn(acc[nt][0], acc[nt][1]);
        if (row1 < M) *(__half2*)(Ch + (size_t)row1 * 128 + col) = __floats2half2_rn(acc[nt][2], acc[nt][3]);
    }
    if (wantStats) {
        #pragma unroll
        for (int nt = 0; nt < 16; ++nt) {
            float s0 = acc[nt][0] + acc[nt][2];
            float s1 = acc[nt][1] + acc[nt][3];
            float q0 = acc[nt][0]*acc[nt][0] + acc[nt][2]*acc[nt][2];
            float q1 = acc[nt][1]*acc[nt][1] + acc[nt][3]*acc[nt][3];
            #pragma unroll
            for (int o = 4; o < 32; o <<= 1) {
                s0 += __shfl_xor_sync(0xffffffffu, s0, o);
                s1 += __shfl_xor_sync(0xffffffffu, s1, o);
                q0 += __shfl_xor_sync(0xffffffffu, q0, o);
                q1 += __shfl_xor_sync(0xffffffffu, q1, o);
            }
            if (lane < 4) {
                int c0 = nt * 8 + lane * 2;
                atomicAdd(&sbs[c0],     s0); atomicAdd(&sbq[c0],     q0);
                atomicAdd(&sbs[c0 + 1], s1); atomicAdd(&sbq[c0 + 1], q1);
            }
        }
        __syncthreads();
        if (tid < 128) {
            atomicAdd(&osum[gy * DD + tid], sbs[tid]);
            atomicAdd(&osumsq[gy * DD + tid], sbq[tid]);
        }
    }
}

// ---------------- final: BN2 + PReLU + mixture over all G (fp16 t2, 2 elems/thread) ----------------
__global__ void k_final(const __half2* __restrict__ t2,
                        const float* __restrict__ s2, const float* __restrict__ q2,
                        const float* __restrict__ gamma2, const float* __restrict__ beta2,
                        const float* __restrict__ alpha_p,
                        const float* __restrict__ mix, float2* __restrict__ out) {
    int idx = blockIdx.x * blockDim.x + threadIdx.x;     // over NN*DD/2 half2
    if (idx >= NN * DD / 2) return;
    int n = idx >> 6;
    int c = (idx & 63) * 2;
    float a = *alpha_p;
    const float invN = 1.0f / (float)NN;
    float r0 = 0.f, r1 = 0.f;
    #pragma unroll
    for (int g = 0; g < GG; ++g) {
        float mu0  = s2[g * DD + c] * invN;
        float var0 = q2[g * DD + c] * invN - mu0 * mu0;
        float rs0  = rsqrtf(var0 + BN_EPS);
        float mu1  = s2[g * DD + c + 1] * invN;
        float var1 = q2[g * DD + c + 1] * invN - mu1 * mu1;
        float rs1  = rsqrtf(var1 + BN_EPS);
        float2 t = __half22float2(t2[(size_t)g * (NN * DD / 2) + idx]);
        float v0 = (t.x - mu0) * rs0 * gamma2[g * DD + c]     + beta2[g * DD + c];
        float v1 = (t.y - mu1) * rs1 * gamma2[g * DD + c + 1] + beta2[g * DD + c + 1];
        v0 = (v0 > 0.f) ? v0 : a * v0;
        v1 = (v1 > 0.f) ? v1 : a * v1;
        float m = mix[(size_t)n * GG + g];
        r0 += m * v0;
        r1 += m * v1;
    }
    out[idx] = make_float2(r0, r1);
}

// ---------------- launch ----------------
extern "C" void kernel_launch(void* const* d_in, const int* in_sizes, int n_in,
                              void* d_out, int out_size) {
    const float* x      = (const float*)d_in[0];
    const int*   ei     = (const int*)d_in[1];
    const float* W1     = (const float*)d_in[2];
    const float* W2     = (const float*)d_in[4];
    const float* gamma1 = (const float*)d_in[6];
    const float* beta1  = (const float*)d_in[7];
    const float* gamma2 = (const float*)d_in[8];
    const float* beta2  = (const float*)d_in[9];
    const float* alpha  = (const float*)d_in[10];
    const float* mixe   = (const float*)d_in[11];
    float*       out    = (float*)d_out;

    void* p;
    cudaGetSymbolAddress(&p, g_cnt);    int* cnt    = (int*)p;
    cudaGetSymbolAddress(&p, g_rowptr); int* rowptr = (int*)p;
    cudaGetSymbolAddress(&p, g_cursor); int* cursor = (int*)p;
    cudaGetSymbolAddress(&p, g_bsum);   int* bsum   = (int*)p;
    cudaGetSymbolAddress(&p, g_esrc);   int* esrc   = (int*)p;
    cudaGetSymbolAddress(&p, g_enorm);  float* enorm= (float*)p;
    cudaGetSymbolAddress(&p, g_dinv);   float* dinv = (float*)p;
    cudaGetSymbolAddress(&p, g_xa);     float* xa   = (float*)p;
    cudaGetSymbolAddress(&p, g_z1);     __half* z1  = (__half*)p;
    cudaGetSymbolAddress(&p, g_h2);     __half* h2  = (__half*)p;
    cudaGetSymbolAddress(&p, g_t2);     __half* t2  = (__half*)p;
    cudaGetSymbolAddress(&p, g_mix);    float* mix  = (float*)p;
    cudaGetSymbolAddress(&p, g_s1);     float* s1   = (float*)p;
    cudaGetSymbolAddress(&p, g_q1);     float* q1   = (float*)p;
    cudaGetSymbolAddress(&p, g_s2);     float* s2   = (float*)p;
    cudaGetSymbolAddress(&p, g_q2);     float* q2   = (float*)p;
    cudaGetSymbolAddress(&p, g_w1h);    __half* w1h = (__half*)p;
    cudaGetSymbolAddress(&p, g_w1l);    __half* w1l = (__half*)p;
    cudaGetSymbolAddress(&p, g_w2h);    __half* w2h = (__half*)p;
    cudaGetSymbolAddress(&p, g_w2l);    __half* w2l = (__half*)p;

    const int* row = ei;
    const int* col = ei + EE;

    const int T = 256;
    const int gN    = (NN + T) / T;
    const int gE    = (EE + T - 1) / T;
    const int gHM   = (EE + NN + 2 * GG * DD * DD + T - 1) / T;
    const int gFin  = (NN * DD / 2 + T - 1) / T;
    const int gRow  = (NN + 127) / 128;                    // 391
    const int nScan = (NN + 1 + 511) / 512;                // 98
    const int gGath = (NN + 63) / 64;                      // 782

    cudaFuncSetAttribute(k_gemm_mma, cudaFuncAttributeMaxDynamicSharedMemorySize, GT_SMEM);

    // setup: CSR + norm + softmax + weight split (recomputed per call)
    k_zero<<<gN, T>>>(cnt, s1, q1, s2, q2);
    k_hist_misc<<<gHM, T>>>(col, cnt, mixe, mix, W1, w1h, w1l, W2, w2h, w2l);
    k_scan1<<<nScan, 512>>>(cnt, rowptr, bsum, dinv);
    k_scan3<<<nScan, 512>>>(rowptr, bsum, cursor, nScan);
    k_place<<<gE, T>>>(row, col, dinv, cursor, esrc, enorm);

    // shared layer-1 propagate: xa = P @ x (fp32)
    k_gather<<<gGath, T>>>((const float4*)x, (float4*)xa, rowptr, esrc, enorm, dinv);

    // layer 1 (all G): z1[g] = xa @ W1[g]^T (fp16 out), fused stats (fp32) -> s1/q1
    k_gemm_mma<<<dim3(gRow, GG), T, GT_SMEM>>>(
        xa, nullptr, w1h, w1l, z1, NN,
        nullptr, nullptr, nullptr, nullptr, nullptr, 0,
        s1, q1, 1, 0 /* shared A */);

    // layer 2 (all G): h2[g] = prelu(BN(z1[g])) @ W2[g]^T (fp16 in/out), BN fused in A-load
    k_gemm_mma<<<dim3(gRow, GG), T, GT_SMEM>>>(
        nullptr, z1, w2h, w2l, h2, NN,
        s1, q1, gamma1, beta1, alpha, 1,
        nullptr, nullptr, 0, (size_t)NN * DD);

    // propagate (all G): t2[g] = P @ h2[g] (fp16 in/out, fp32 acc), fused stats -> s2/q2
    k_gather_h<<<dim3(gGath, GG), T>>>((const uint2*)h2, (uint2*)t2,
                                       rowptr, esrc, enorm, dinv, s2, q2);

    // final: BN2 + PReLU + softmax-mix accumulate, single pass (fp16 t2)
    k_final<<<gFin, T>>>((const __half2*)t2, s2, q2, gamma2, beta2, alpha, mix, (float2*)out);
}

// round 16
// speedup vs baseline: 1.2243x; 1.1113x over previous
#include <cuda_runtime.h>
#include <cuda_bf16.h>
#include <cuda_fp16.h>
#include <cstdint>
#include <cstddef>

#define NN 50000
#define EE 800000
#define DD 128
#define GG 4
#define BN_EPS 1e-5f

// ---------------- static scratch (no allocations allowed) ----------------
__device__ int   g_cnt[NN + 1];
__device__ int   g_rowptr[NN + 1];
__device__ int   g_cursor[NN];
__device__ int   g_bsum[128];
__device__ int   g_esrc[EE];
__device__ float g_enorm[EE];
__device__ float g_dinv[NN];
__device__ float g_xa[(size_t)NN * DD];        // P @ x, fp32
__device__ __half g_z1[(size_t)GG * NN * DD];  // fp16 (BN1 stats stay fp32)
__device__ __half g_h2[(size_t)GG * NN * DD];  // fp16 edge-read stream
__device__ __half g_t2[(size_t)GG * NN * DD];  // fp16 (BN2 stats stay fp32)
__device__ float g_mix[(size_t)NN * GG];
__device__ float g_s1[GG * DD];
__device__ float g_q1[GG * DD];
__device__ float g_s2[GG * DD];
__device__ float g_q2[GG * DD];
__device__ __half g_w1h[(size_t)GG * DD * DD]; // fp16 weight hi
__device__ __half g_w1l[(size_t)GG * DD * DD]; // fp16 weight residual
__device__ __half g_w2h[(size_t)GG * DD * DD];
__device__ __half g_w2l[(size_t)GG * DD * DD];

// ---------------- setup ----------------
__global__ void k_zero(int* cnt, float* s1, float* q1, float* s2, float* q2) {
    int i = blockIdx.x * blockDim.x + threadIdx.x;
    if (i <= NN) cnt[i] = 0;
    if (i < GG * DD) { s1[i] = 0.f; q1[i] = 0.f; s2[i] = 0.f; q2[i] = 0.f; }
}

// merged: histogram | softmax(mix_embed) | split W1 | split W2  (range-keyed)
__global__ void k_hist_misc(const int* __restrict__ col, int* cnt,
                            const float* __restrict__ me, float* __restrict__ mix,
                            const float* __restrict__ W1, __half* __restrict__ w1h, __half* __restrict__ w1l,
                            const float* __restrict__ W2, __half* __restrict__ w2h, __half* __restrict__ w2l) {
    int i = blockIdx.x * blockDim.x + threadIdx.x;
    if (i < EE) {
        int c = col[i];
        if ((unsigned)c < (unsigned)NN) atomicAdd(&cnt[c], 1);
        return;
    }
    int m = i - EE;
    if (m < NN) {
        float m0 = me[m*4+0], m1 = me[m*4+1], m2 = me[m*4+2], m3 = me[m*4+3];
        float mx = fmaxf(fmaxf(m0, m1), fmaxf(m2, m3));
        float e0 = expf(m0-mx), e1 = expf(m1-mx), e2 = expf(m2-mx), e3 = expf(m3-mx);
        float inv = 1.0f / (e0 + e1 + e2 + e3);
        mix[m*4+0] = e0*inv; mix[m*4+1] = e1*inv; mix[m*4+2] = e2*inv; mix[m*4+3] = e3*inv;
        return;
    }
    int j = m - NN;
    const float* W;
    __half *Wh, *Wl;
    if (j < GG * DD * DD) { W = W1; Wh = w1h; Wl = w1l; }
    else {
        j -= GG * DD * DD;
        if (j >= GG * DD * DD) return;
        W = W2; Wh = w2h; Wl = w2l;
    }
    int g = j >> 14, rem = j & 16383, n = rem >> 7, k = rem & 127;
    float w = W[(g << 14) + (k << 7) + n];          // transpose to [g][n][k]
    __half h = __float2half_rn(w);
    Wh[j] = h;
    Wl[j] = __float2half_rn(w - __half2float(h));   // 22-bit effective precision
}

__global__ void k_scan1(const int* __restrict__ cnt, int* __restrict__ rowptr,
                        int* __restrict__ bsum, float* __restrict__ dinv) {
    __shared__ int s[512];
    int tid = threadIdx.x;
    int i = blockIdx.x * 512 + tid;
    int v = (i <= NN) ? cnt[i] : 0;
    if (i < NN) dinv[i] = rsqrtf((float)v + 1.0f);   // +1 self-loop
    s[tid] = v;
    __syncthreads();
    #pragma unroll
    for (int off = 1; off < 512; off <<= 1) {
        int t = (tid >= off) ? s[tid - off] : 0;
        __syncthreads();
        s[tid] += t;
        __syncthreads();
    }
    if (i <= NN) rowptr[i] = s[tid] - v;
    if (tid == 511) bsum[blockIdx.x] = s[511];
}
__global__ void k_scan3(int* __restrict__ rowptr, const int* __restrict__ bsum,
                        int* __restrict__ cursor, int nb) {
    __shared__ int s[128];
    int tid = threadIdx.x;
    if (tid < 128) {
        int v = (tid < nb) ? bsum[tid] : 0;
        s[tid] = v;
    }
    __syncthreads();
    if (tid < 128) {
        #pragma unroll
        for (int off = 1; off < 128; off <<= 1) {
            int t = (tid >= off) ? s[tid - off] : 0;
            __syncthreads();
            s[tid] += t;
            __syncthreads();
        }
    } else {
        #pragma unroll
        for (int off = 1; off < 128; off <<= 1) { __syncthreads(); __syncthreads(); }
    }
    int boff = s[blockIdx.x] - bsum[blockIdx.x];
    int i = blockIdx.x * 512 + tid;
    if (i <= NN) {
        int r = rowptr[i] + boff;
        rowptr[i] = r;
        if (i < NN) cursor[i] = r;
    }
}
__global__ void k_place(const int* __restrict__ row, const int* __restrict__ col,
                        const float* __restrict__ dinv,
                        int* __restrict__ cursor, int* __restrict__ esrc, float* __restrict__ enorm) {
    int e = blockIdx.x * blockDim.x + threadIdx.x;
    if (e >= EE) return;
    int r = row[e], c = col[e];
    if ((unsigned)r >= (unsigned)NN || (unsigned)c >= (unsigned)NN) return;
    int pos = atomicAdd(&cursor[c], 1);
    esrc[pos] = r;
    enorm[pos] = dinv[r] * dinv[c];
}

// ---------------- gather fp32 (xa = P @ x), edge loop unrolled x8 ----------------
__global__ void __launch_bounds__(256) k_gather(
    const float4* __restrict__ src, float4* __restrict__ dst,
    const int* __restrict__ rowptr, const int* __restrict__ esrc,
    const float* __restrict__ enorm, const float* __restrict__ dinv)
{
    int tid = threadIdx.x, wid = tid >> 5, lane = tid & 31;
    int n0 = blockIdx.x * 64 + wid * 8;
    for (int i = 0; i < 8; ++i) {
        int n = n0 + i;
        if (n >= NN) break;
        float dw = dinv[n];
        float w0 = dw * dw;
        float4 a = src[(size_t)n * 32 + lane];
        float4 acc = make_float4(a.x * w0, a.y * w0, a.z * w0, a.w * w0);
        int j0 = rowptr[n], j1 = rowptr[n + 1];
        int j = j0;
        for (; j + 8 <= j1; j += 8) {
            float4 v[8];
            float u[8];
            #pragma unroll
            for (int t = 0; t < 8; ++t) {
                v[t] = src[(size_t)esrc[j+t] * 32 + lane];
                u[t] = enorm[j+t];
            }
            #pragma unroll
            for (int t = 0; t < 8; ++t) {
                acc.x += u[t]*v[t].x; acc.y += u[t]*v[t].y;
                acc.z += u[t]*v[t].z; acc.w += u[t]*v[t].w;
            }
        }
        for (; j < j1; ++j) {
            int sn = esrc[j];
            float w = enorm[j];
            float4 v = src[(size_t)sn * 32 + lane];
            acc.x += w * v.x; acc.y += w * v.y; acc.z += w * v.z; acc.w += w * v.w;
        }
        dst[(size_t)n * 32 + lane] = acc;
    }
}

// ---------------- gather fp16 src/dst (t2 = P @ h2) + fused BN stats ----------------
__device__ __forceinline__ float4 h2f4(uint2 r) {
    __half2 a = *(__half2*)&r.x, b = *(__half2*)&r.y;
    float2 fa = __half22float2(a), fb = __half22float2(b);
    return make_float4(fa.x, fa.y, fb.x, fb.y);
}
__device__ __forceinline__ uint2 f4h2(float4 v) {
    __half2 a = __floats2half2_rn(v.x, v.y);
    __half2 b = __floats2half2_rn(v.z, v.w);
    uint2 r;
    r.x = *(uint32_t*)&a; r.y = *(uint32_t*)&b;
    return r;
}

__global__ void __launch_bounds__(256) k_gather_h(
    const uint2* __restrict__ src, uint2* __restrict__ dst,
    const int* __restrict__ rowptr, const int* __restrict__ esrc,
    const float* __restrict__ enorm, const float* __restrict__ dinv,
    float* __restrict__ osum, float* __restrict__ osumsq)
{
    __shared__ float sbs[128], sbq[128];
    int gy = blockIdx.y;
    src += (size_t)gy * NN * 32;        // row = 32 uint2 (128 half)
    dst += (size_t)gy * NN * 32;
    int tid = threadIdx.x, wid = tid >> 5, lane = tid & 31;
    if (tid < 128) { sbs[tid] = 0.f; sbq[tid] = 0.f; }
    __syncthreads();

    float s[4] = {0.f, 0.f, 0.f, 0.f}, q[4] = {0.f, 0.f, 0.f, 0.f};
    int n0 = blockIdx.x * 64 + wid * 8;
    for (int i = 0; i < 8; ++i) {
        int n = n0 + i;
        if (n >= NN) break;
        float dw = dinv[n];
        float w0 = dw * dw;
        float4 a = h2f4(src[(size_t)n * 32 + lane]);
        float4 acc = make_float4(a.x * w0, a.y * w0, a.z * w0, a.w * w0);
        int j0 = rowptr[n], j1 = rowptr[n + 1];
        int j = j0;
        for (; j + 8 <= j1; j += 8) {
            uint2 rv[8];
            float u[8];
            #pragma unroll
            for (int t = 0; t < 8; ++t) {
                rv[t] = src[(size_t)esrc[j+t] * 32 + lane];
                u[t]  = enorm[j+t];
            }
            #pragma unroll
            for (int t = 0; t < 8; ++t) {
                float4 v = h2f4(rv[t]);
                acc.x += u[t]*v.x; acc.y += u[t]*v.y;
                acc.z += u[t]*v.z; acc.w += u[t]*v.w;
            }
        }
        for (; j + 4 <= j1; j += 4) {
            uint2 rv[4];
            float u[4];
            #pragma unroll
            for (int t = 0; t < 4; ++t) {
                rv[t] = src[(size_t)esrc[j+t] * 32 + lane];
                u[t]  = enorm[j+t];
            }
            #pragma unroll
            for (int t = 0; t < 4; ++t) {
                float4 v = h2f4(rv[t]);
                acc.x += u[t]*v.x; acc.y += u[t]*v.y;
                acc.z += u[t]*v.z; acc.w += u[t]*v.w;
            }
        }
        for (; j < j1; ++j) {
            float w = enorm[j];
            float4 v = h2f4(src[(size_t)esrc[j] * 32 + lane]);
            acc.x += w * v.x; acc.y += w * v.y; acc.z += w * v.z; acc.w += w * v.w;
        }
        dst[(size_t)n * 32 + lane] = f4h2(acc);
        s[0] += acc.x; q[0] += acc.x * acc.x;
        s[1] += acc.y; q[1] += acc.y * acc.y;
        s[2] += acc.z; q[2] += acc.z * acc.z;
        s[3] += acc.w; q[3] += acc.w * acc.w;
    }
    int c = lane * 4;
    atomicAdd(&sbs[c + 0], s[0]); atomicAdd(&sbq[c + 0], q[0]);
    atomicAdd(&sbs[c + 1], s[1]); atomicAdd(&sbq[c + 1], q[1]);
    atomicAdd(&sbs[c + 2], s[2]); atomicAdd(&sbq[c + 2], q[2]);
    atomicAdd(&sbs[c + 3], s[3]); atomicAdd(&sbq[c + 3], q[3]);
    __syncthreads();
    if (tid < 128) {
        atomicAdd(&osum[gy * DD + tid], sbs[tid]);
        atomicAdd(&osumsq[gy * DD + tid], sbq[tid]);
    }
}

// ---------------- GEMM: C = A @ W^T, mma.sync fp16 2-term weight split ----------------
// Warp tiling: 8 warps as 4 row-groups x 2 col-groups; warp = 32 rows x 64 cols.
// smem: WH | WL | A, each 128 rows x 136 fp16 (272B row stride)
#define TROW 272
#define SM_WH 0
#define SM_WL (SM_WH + 128 * TROW)
#define SM_A  (SM_WL + 128 * TROW)
#define GT_SMEM (SM_A + 128 * TROW)

__device__ __forceinline__ void mma_f16(float* d, const uint32_t* a, const uint32_t* b) {
    asm volatile(
        "mma.sync.aligned.m16n8k16.row.col.f32.f16.f16.f32 "
        "{%0,%1,%2,%3}, {%4,%5,%6,%7}, {%8,%9}, {%0,%1,%2,%3};"
        : "+f"(d[0]), "+f"(d[1]), "+f"(d[2]), "+f"(d[3])
        : "r"(a[0]), "r"(a[1]), "r"(a[2]), "r"(a[3]), "r"(b[0]), "r"(b[1]));
}

// A input: fp32 (Af) or fp16 (Ah16) — exactly one non-null. Output: fp16 (Ch).
__global__ void __launch_bounds__(256) k_gemm_mma(
    const float* __restrict__ Af, const __half* __restrict__ Ah16,
    const __half* __restrict__ Bh, const __half* __restrict__ Bl,
    __half* __restrict__ Ch, int M,
    const float* __restrict__ bn_sum, const float* __restrict__ bn_sumsq,
    const float* __restrict__ gamma, const float* __restrict__ beta,
    const float* __restrict__ alpha_p, int applyBN,
    float* osum, float* osumsq, int wantStats, size_t aStride)
{
    extern __shared__ char sm[];
    __shared__ float sbs[128], sbq[128];
    int gy = blockIdx.y;
    if (Af)   Af   += (size_t)gy * aStride;
    if (Ah16) Ah16 += (size_t)gy * aStride;
    Bh += (size_t)gy * (DD * DD);
    Bl += (size_t)gy * (DD * DD);
    Ch += (size_t)gy * NN * DD;
    if (applyBN) {
        bn_sum += gy * DD; bn_sumsq += gy * DD;
        gamma  += gy * DD; beta     += gy * DD;
    }
    int tid = threadIdx.x, wid = tid >> 5, lane = tid & 31;

    if (wantStats && tid < 128) { sbs[tid] = 0.f; sbq[tid] = 0.f; }

    // --- load W tiles (fp16 hi + residual, [n][k]) ---
    {
        int n = tid >> 1;
        int k0 = (tid & 1) * 64;
        const uint4* bh = (const uint4*)(Bh + (size_t)n * 128 + k0);
        const uint4* bl = (const uint4*)(Bl + (size_t)n * 128 + k0);
        char* wh = sm + SM_WH + n * TROW + k0 * 2;
        char* wl = sm + SM_WL + n * TROW + k0 * 2;
        #pragma unroll
        for (int i = 0; i < 8; ++i) {
            *(uint4*)(wh + i * 16) = bh[i];
            *(uint4*)(wl + i * 16) = bl[i];
        }
    }
    // --- load A rows, optional fused BN+PReLU, round to fp16 in smem ---
    {
        int r = tid >> 1;
        int k0 = (tid & 1) * 64;
        int gr = blockIdx.x * 128 + r;
        bool valid = gr < M;
        float alpha = applyBN ? *alpha_p : 0.f;
        const float invN = 1.0f / (float)NN;
        char* ap = sm + SM_A + r * TROW + k0 * 2;
        #pragma unroll
        for (int i = 0; i < 16; ++i) {
            int k = k0 + i * 4;
            float v[4] = {0.f, 0.f, 0.f, 0.f};
            if (valid) {
                if (Ah16) {
                    uint2 hv = *(const uint2*)(Ah16 + (size_t)gr * 128 + k);
                    __half2* hh = (__half2*)&hv;
                    float2 f0 = __half22float2(hh[0]), f1 = __half22float2(hh[1]);
                    v[0] = f0.x; v[1] = f0.y; v[2] = f1.x; v[3] = f1.y;
                } else {
                    float4 f = *(const float4*)(Af + (size_t)gr * 128 + k);
                    v[0] = f.x; v[1] = f.y; v[2] = f.z; v[3] = f.w;
                }
            }
            if (applyBN) {
                #pragma unroll
                for (int j = 0; j < 4; ++j) {
                    int kk = k + j;
                    float mu  = bn_sum[kk] * invN;
                    float var = bn_sumsq[kk] * invN - mu * mu;
                    float rs  = rsqrtf(var + BN_EPS);
                    float z = (v[j] - mu) * rs * gamma[kk] + beta[kk];
                    v[j] = (z > 0.f) ? z : alpha * z;
                }
            }
            __half2 p0 = __floats2half2_rn(v[0], v[1]);
            __half2 p1 = __floats2half2_rn(v[2], v[3]);
            *(uint2*)(ap + i * 8) = make_uint2(*(uint32_t*)&p0, *(uint32_t*)&p1);
        }
    }
    __syncthreads();

    // --- warp MMA: warp (rg, cg) owns rows [rg*32, +32), cols [cg*64, +64) ---
    int rg = wid >> 1, cg = wid & 1;
    float acc[2][8][4];
    #pragma unroll
    for (int rt = 0; rt < 2; ++rt)
        #pragma unroll
        for (int nt = 0; nt < 8; ++nt)
            #pragma unroll
            for (int qq = 0; qq < 4; ++qq) acc[rt][nt][qq] = 0.f;

    int qrow = lane >> 2;
    int kb   = (lane & 3) * 4;

    #pragma unroll
    for (int kk = 0; kk < 8; ++kk) {
        int kbyte = kk * 32 + kb;
        uint32_t a_[2][4];
        #pragma unroll
        for (int rt = 0; rt < 2; ++rt) {
            const char* arow = sm + SM_A + (rg * 32 + rt * 16 + qrow) * TROW + kbyte;
            a_[rt][0] = *(const uint32_t*)(arow);
            a_[rt][1] = *(const uint32_t*)(arow + 8 * TROW);
            a_[rt][2] = *(const uint32_t*)(arow + 16);
            a_[rt][3] = *(const uint32_t*)(arow + 8 * TROW + 16);
        }
        #pragma unroll
        for (int nt = 0; nt < 8; ++nt) {
            int ncol = cg * 64 + nt * 8;
            const char* brow  = sm + SM_WH + (ncol + qrow) * TROW + kbyte;
            const char* browl = sm + SM_WL + (ncol + qrow) * TROW + kbyte;
            uint32_t b_h[2], b_l[2];
            b_h[0] = *(const uint32_t*)(brow);
            b_h[1] = *(const uint32_t*)(brow + 16);
            b_l[0] = *(const uint32_t*)(browl);
            b_l[1] = *(const uint32_t*)(browl + 16);
            #pragma unroll
            for (int rt = 0; rt < 2; ++rt) {
                mma_f16(acc[rt][nt], a_[rt], b_h);
                mma_f16(acc[rt][nt], a_[rt], b_l);
            }
        }
    }

    // --- epilogue: store fp16 + optional fused BN stats ---
    int colb = (lane & 3) * 2;
    #pragma unroll
    for (int rt = 0; rt < 2; ++rt) {
        int row0 = blockIdx.x * 128 + rg * 32 + rt * 16 + qrow;
        int row1 = row0 + 8;
        #pragma unroll
        for (int nt = 0; nt < 8; ++nt) {
            int col = cg * 64 + nt * 8 + colb;
            if (row0 < M) *(__half2*)(Ch + (size_t)row0 * 128 + col) = __floats2half2_rn(acc[rt][nt][0], acc[rt][nt][1]);
            if (row1 < M) *(__half2*)(Ch + (size_t)row1 * 128 + col) = __floats2half2_rn(acc[rt][nt][2], acc[rt][nt][3]);
        }
    }
    if (wantStats) {
        #pragma unroll
        for (int nt = 0; nt < 8; ++nt) {
            float s0 = acc[0][nt][0] + acc[0][nt][2] + acc[1][nt][0] + acc[1][nt][2];
            float s1 = acc[0][nt][1] + acc[0][nt][3] + acc[1][nt][1] + acc[1][nt][3];
            float q0 = acc[0][nt][0]*acc[0][nt][0] + acc[0][nt][2]*acc[0][nt][2]
                     + acc[1][nt][0]*acc[1][nt][0] + acc[1][nt][2]*acc[1][nt][2];
            float q1 = acc[0][nt][1]*acc[0][nt][1] + acc[0][nt][3]*acc[0][nt][3]
                     + acc[1][nt][1]*acc[1][nt][1] + acc[1][nt][3]*acc[1][nt][3];
            #pragma unroll
            for (int o = 4; o < 32; o <<= 1) {
                s0 += __shfl_xor_sync(0xffffffffu, s0, o);
                s1 += __shfl_xor_sync(0xffffffffu, s1, o);
                q0 += __shfl_xor_sync(0xffffffffu, q0, o);
                q1 += __shfl_xor_sync(0xffffffffu, q1, o);
            }
            if (lane < 4) {
                int c0 = cg * 64 + nt * 8 + lane * 2;
                atomicAdd(&sbs[c0],     s0); atomicAdd(&sbq[c0],     q0);
                atomicAdd(&sbs[c0 + 1], s1); atomicAdd(&sbq[c0 + 1], q1);
            }
        }
        __syncthreads();
        if (tid < 128) {
            atomicAdd(&osum[gy * DD + tid], sbs[tid]);
            atomicAdd(&osumsq[gy * DD + tid], sbq[tid]);
        }
    }
}

// ---------------- final: BN2 + PReLU + mixture over all G (fp16 t2, 2 elems/thread) ----------------
__global__ void k_final(const __half2* __restrict__ t2,
                        const float* __restrict__ s2, const float* __restrict__ q2,
                        const float* __restrict__ gamma2, const float* __restrict__ beta2,
                        const float* __restrict__ alpha_p,
                        const float* __restrict__ mix, float2* __restrict__ out) {
    int idx = blockIdx.x * blockDim.x + threadIdx.x;     // over NN*DD/2 half2
    if (idx >= NN * DD / 2) return;
    int n = idx >> 6;
    int c = (idx & 63) * 2;
    float a = *alpha_p;
    const float invN = 1.0f / (float)NN;
    float r0 = 0.f, r1 = 0.f;
    #pragma unroll
    for (int g = 0; g < GG; ++g) {
        float mu0  = s2[g * DD + c] * invN;
        float var0 = q2[g * DD + c] * invN - mu0 * mu0;
        float rs0  = rsqrtf(var0 + BN_EPS);
        float mu1  = s2[g * DD + c + 1] * invN;
        float var1 = q2[g * DD + c + 1] * invN - mu1 * mu1;
        float rs1  = rsqrtf(var1 + BN_EPS);
        float2 t = __half22float2(t2[(size_t)g * (NN * DD / 2) + idx]);
        float v0 = (t.x - mu0) * rs0 * gamma2[g * DD + c]     + beta2[g * DD + c];
        float v1 = (t.y - mu1) * rs1 * gamma2[g * DD + c + 1] + beta2[g * DD + c + 1];
        v0 = (v0 > 0.f) ? v0 : a * v0;
        v1 = (v1 > 0.f) ? v1 : a * v1;
        float m = mix[(size_t)n * GG + g];
        r0 += m * v0;
        r1 += m * v1;
    }
    out[idx] = make_float2(r0, r1);
}

// ---------------- launch ----------------
extern "C" void kernel_launch(void* const* d_in, const int* in_sizes, int n_in,
                              void* d_out, int out_size) {
    const float* x      = (const float*)d_in[0];
    const int*   ei     = (const int*)d_in[1];
    const float* W1     = (const float*)d_in[2];
    const float* W2     = (const float*)d_in[4];
    const float* gamma1 = (const float*)d_in[6];
    const float* beta1  = (const float*)d_in[7];
    const float* gamma2 = (const float*)d_in[8];
    const float* beta2  = (const float*)d_in[9];
    const float* alpha  = (const float*)d_in[10];
    const float* mixe   = (const float*)d_in[11];
    float*       out    = (float*)d_out;

    void* p;
    cudaGetSymbolAddress(&p, g_cnt);    int* cnt    = (int*)p;
    cudaGetSymbolAddress(&p, g_rowptr); int* rowptr = (int*)p;
    cudaGetSymbolAddress(&p, g_cursor); int* cursor = (int*)p;
    cudaGetSymbolAddress(&p, g_bsum);   int* bsum   = (int*)p;
    cudaGetSymbolAddress(&p, g_esrc);   int* esrc   = (int*)p;
    cudaGetSymbolAddress(&p, g_enorm);  float* enorm= (float*)p;
    cudaGetSymbolAddress(&p, g_dinv);   float* dinv = (float*)p;
    cudaGetSymbolAddress(&p, g_xa);     float* xa   = (float*)p;
    cudaGetSymbolAddress(&p, g_z1);     __half* z1  = (__half*)p;
    cudaGetSymbolAddress(&p, g_h2);     __half* h2  = (__half*)p;
    cudaGetSymbolAddress(&p, g_t2);     __half* t2  = (__half*)p;
    cudaGetSymbolAddress(&p, g_mix);    float* mix  = (float*)p;
    cudaGetSymbolAddress(&p, g_s1);     float* s1   = (float*)p;
    cudaGetSymbolAddress(&p, g_q1);     float* q1   = (float*)p;
    cudaGetSymbolAddress(&p, g_s2);     float* s2   = (float*)p;
    cudaGetSymbolAddress(&p, g_q2);     float* q2   = (float*)p;
    cudaGetSymbolAddress(&p, g_w1h);    __half* w1h = (__half*)p;
    cudaGetSymbolAddress(&p, g_w1l);    __half* w1l = (__half*)p;
    cudaGetSymbolAddress(&p, g_w2h);    __half* w2h = (__half*)p;
    cudaGetSymbolAddress(&p, g_w2l);    __half* w2l = (__half*)p;

    const int* row = ei;
    const int* col = ei + EE;

    const int T = 256;
    const int gN    = (NN + T) / T;
    const int gE    = (EE + T - 1) / T;
    const int gHM   = (EE + NN + 2 * GG * DD * DD + T - 1) / T;
    const int gFin  = (NN * DD / 2 + T - 1) / T;
    const int gRow  = (NN + 127) / 128;                    // 391
    const int nScan = (NN + 1 + 511) / 512;                // 98
    const int gGath = (NN + 63) / 64;                      // 782

    cudaFuncSetAttribute(k_gemm_mma, cudaFuncAttributeMaxDynamicSharedMemorySize, GT_SMEM);

    // setup: CSR + norm + softmax + weight split (recomputed per call)
    k_zero<<<gN, T>>>(cnt, s1, q1, s2, q2);
    k_hist_misc<<<gHM, T>>>(col, cnt, mixe, mix, W1, w1h, w1l, W2, w2h, w2l);
    k_scan1<<<nScan, 512>>>(cnt, rowptr, bsum, dinv);
    k_scan3<<<nScan, 512>>>(rowptr, bsum, cursor, nScan);
    k_place<<<gE, T>>>(row, col, dinv, cursor, esrc, enorm);

    // shared layer-1 propagate: xa = P @ x (fp32)
    k_gather<<<gGath, T>>>((const float4*)x, (float4*)xa, rowptr, esrc, enorm, dinv);

    // layer 1 (all G): z1[g] = xa @ W1[g]^T (fp16 out), fused stats (fp32) -> s1/q1
    k_gemm_mma<<<dim3(gRow, GG), T, GT_SMEM>>>(
        xa, nullptr, w1h, w1l, z1, NN,
        nullptr, nullptr, nullptr, nullptr, nullptr, 0,
        s1, q1, 1, 0 /* shared A */);

    // layer 2 (all G): h2[g] = prelu(BN(z1[g])) @ W2[g]^T (fp16 in/out), BN fused in A-load
    k_gemm_mma<<<dim3(gRow, GG), T, GT_SMEM>>>(
        nullptr, z1, w2h, w2l, h2, NN,
        s1, q1, gamma1, beta1, alpha, 1,
        nullptr, nullptr, 0, (size_t)NN * DD);

    // propagate (all G): t2[g] = P @ h2[g] (fp16 in/out, fp32 acc), fused stats -> s2/q2
    k_gather_h<<<dim3(gGath, GG), T>>>((const uint2*)h2, (uint2*)t2,
                                       rowptr, esrc, enorm, dinv, s2, q2);

    // final: BN2 + PReLU + softmax-mix accumulate, single pass (fp16 t2)
    k_final<<<gFin, T>>>((const __half2*)t2, s2, q2, gamma2, beta2, alpha, mix, (float2*)out);
}

// round 17
// speedup vs baseline: 1.3034x; 1.0646x over previous
#include <cuda_runtime.h>
#include <cuda_bf16.h>
#include <cuda_fp16.h>
#include <cstdint>
#include <cstddef>

#define NN 50000
#define EE 800000
#define DD 128
#define GG 4
#define BN_EPS 1e-5f

// ---------------- static scratch (no allocations allowed) ----------------
__device__ int   g_cnt[NN + 1];
__device__ int   g_rowptr[NN + 1];
__device__ int   g_cursor[NN];
__device__ int   g_bsum[128];
__device__ int   g_esrc[EE];
__device__ float g_enorm[EE];
__device__ float g_dinv[NN];
__device__ float g_xa[(size_t)NN * DD];        // P @ x, fp32
__device__ __half g_z1[(size_t)GG * NN * DD];  // fp16 (BN1 stats stay fp32)
__device__ __half g_h2[(size_t)GG * NN * DD];  // fp16 edge-read stream
__device__ __half g_t2[(size_t)GG * NN * DD];  // fp16 (BN2 stats stay fp32)
__device__ float g_mix[(size_t)NN * GG];
__device__ float g_s1[GG * DD];
__device__ float g_q1[GG * DD];
__device__ float g_s2[GG * DD];
__device__ float g_q2[GG * DD];
__device__ __half g_w1h[(size_t)GG * DD * DD]; // fp16 weight hi
__device__ __half g_w1l[(size_t)GG * DD * DD]; // fp16 weight residual
__device__ __half g_w2h[(size_t)GG * DD * DD];
__device__ __half g_w2l[(size_t)GG * DD * DD];

// ---------------- setup ----------------
__global__ void k_zero(int* cnt, float* s1, float* q1, float* s2, float* q2) {
    int i = blockIdx.x * blockDim.x + threadIdx.x;
    if (i <= NN) cnt[i] = 0;
    if (i < GG * DD) { s1[i] = 0.f; q1[i] = 0.f; s2[i] = 0.f; q2[i] = 0.f; }
}

// merged: histogram | softmax(mix_embed) | split W1 | split W2  (range-keyed)
__global__ void k_hist_misc(const int* __restrict__ col, int* cnt,
                            const float* __restrict__ me, float* __restrict__ mix,
                            const float* __restrict__ W1, __half* __restrict__ w1h, __half* __restrict__ w1l,
                            const float* __restrict__ W2, __half* __restrict__ w2h, __half* __restrict__ w2l) {
    int i = blockIdx.x * blockDim.x + threadIdx.x;
    if (i < EE) {
        int c = col[i];
        if ((unsigned)c < (unsigned)NN) atomicAdd(&cnt[c], 1);
        return;
    }
    int m = i - EE;
    if (m < NN) {
        float m0 = me[m*4+0], m1 = me[m*4+1], m2 = me[m*4+2], m3 = me[m*4+3];
        float mx = fmaxf(fmaxf(m0, m1), fmaxf(m2, m3));
        float e0 = expf(m0-mx), e1 = expf(m1-mx), e2 = expf(m2-mx), e3 = expf(m3-mx);
        float inv = 1.0f / (e0 + e1 + e2 + e3);
        mix[m*4+0] = e0*inv; mix[m*4+1] = e1*inv; mix[m*4+2] = e2*inv; mix[m*4+3] = e3*inv;
        return;
    }
    int j = m - NN;
    const float* W;
    __half *Wh, *Wl;
    if (j < GG * DD * DD) { W = W1; Wh = w1h; Wl = w1l; }
    else {
        j -= GG * DD * DD;
        if (j >= GG * DD * DD) return;
        W = W2; Wh = w2h; Wl = w2l;
    }
    int g = j >> 14, rem = j & 16383, n = rem >> 7, k = rem & 127;
    float w = W[(g << 14) + (k << 7) + n];          // transpose to [g][n][k]
    __half h = __float2half_rn(w);
    Wh[j] = h;
    Wl[j] = __float2half_rn(w - __half2float(h));   // 22-bit effective precision
}

__global__ void k_scan1(const int* __restrict__ cnt, int* __restrict__ rowptr,
                        int* __restrict__ bsum, float* __restrict__ dinv) {
    __shared__ int s[512];
    int tid = threadIdx.x;
    int i = blockIdx.x * 512 + tid;
    int v = (i <= NN) ? cnt[i] : 0;
    if (i < NN) dinv[i] = rsqrtf((float)v + 1.0f);   // +1 self-loop
    s[tid] = v;
    __syncthreads();
    #pragma unroll
    for (int off = 1; off < 512; off <<= 1) {
        int t = (tid >= off) ? s[tid - off] : 0;
        __syncthreads();
        s[tid] += t;
        __syncthreads();
    }
    if (i <= NN) rowptr[i] = s[tid] - v;
    if (tid == 511) bsum[blockIdx.x] = s[511];
}
__global__ void k_scan3(int* __restrict__ rowptr, const int* __restrict__ bsum,
                        int* __restrict__ cursor, int nb) {
    __shared__ int s[128];
    int tid = threadIdx.x;
    if (tid < 128) {
        int v = (tid < nb) ? bsum[tid] : 0;
        s[tid] = v;
    }
    __syncthreads();
    if (tid < 128) {
        #pragma unroll
        for (int off = 1; off < 128; off <<= 1) {
            int t = (tid >= off) ? s[tid - off] : 0;
            __syncthreads();
            s[tid] += t;
            __syncthreads();
        }
    } else {
        #pragma unroll
        for (int off = 1; off < 128; off <<= 1) { __syncthreads(); __syncthreads(); }
    }
    int boff = s[blockIdx.x] - bsum[blockIdx.x];
    int i = blockIdx.x * 512 + tid;
    if (i <= NN) {
        int r = rowptr[i] + boff;
        rowptr[i] = r;
        if (i < NN) cursor[i] = r;
    }
}
__global__ void k_place(const int* __restrict__ row, const int* __restrict__ col,
                        const float* __restrict__ dinv,
                        int* __restrict__ cursor, int* __restrict__ esrc, float* __restrict__ enorm) {
    int e = blockIdx.x * blockDim.x + threadIdx.x;
    if (e >= EE) return;
    int r = row[e], c = col[e];
    if ((unsigned)r >= (unsigned)NN || (unsigned)c >= (unsigned)NN) return;
    int pos = atomicAdd(&cursor[c], 1);
    esrc[pos] = r;
    enorm[pos] = dinv[r] * dinv[c];
}

// ---------------- gather fp32 (xa = P @ x), edge loop unrolled x8 ----------------
__global__ void __launch_bounds__(256) k_gather(
    const float4* __restrict__ src, float4* __restrict__ dst,
    const int* __restrict__ rowptr, const int* __restrict__ esrc,
    const float* __restrict__ enorm, const float* __restrict__ dinv)
{
    int tid = threadIdx.x, wid = tid >> 5, lane = tid & 31;
    int n0 = blockIdx.x * 64 + wid * 8;
    for (int i = 0; i < 8; ++i) {
        int n = n0 + i;
        if (n >= NN) break;
        float dw = dinv[n];
        float w0 = dw * dw;
        float4 a = src[(size_t)n * 32 + lane];
        float4 acc = make_float4(a.x * w0, a.y * w0, a.z * w0, a.w * w0);
        int j0 = rowptr[n], j1 = rowptr[n + 1];
        int j = j0;
        for (; j + 8 <= j1; j += 8) {
            float4 v[8];
            float u[8];
            #pragma unroll
            for (int t = 0; t < 8; ++t) {
                v[t] = src[(size_t)esrc[j+t] * 32 + lane];
                u[t] = enorm[j+t];
            }
            #pragma unroll
            for (int t = 0; t < 8; ++t) {
                acc.x += u[t]*v[t].x; acc.y += u[t]*v[t].y;
                acc.z += u[t]*v[t].z; acc.w += u[t]*v[t].w;
            }
        }
        for (; j < j1; ++j) {
            int sn = esrc[j];
            float w = enorm[j];
            float4 v = src[(size_t)sn * 32 + lane];
            acc.x += w * v.x; acc.y += w * v.y; acc.z += w * v.z; acc.w += w * v.w;
        }
        dst[(size_t)n * 32 + lane] = acc;
    }
}

// ---------------- gather fp16 src/dst (t2 = P @ h2) + fused BN stats ----------------
__device__ __forceinline__ float4 h2f4(uint2 r) {
    __half2 a = *(__half2*)&r.x, b = *(__half2*)&r.y;
    float2 fa = __half22float2(a), fb = __half22float2(b);
    return make_float4(fa.x, fa.y, fb.x, fb.y);
}
__device__ __forceinline__ uint2 f4h2(float4 v) {
    __half2 a = __floats2half2_rn(v.x, v.y);
    __half2 b = __floats2half2_rn(v.z, v.w);
    uint2 r;
    r.x = *(uint32_t*)&a; r.y = *(uint32_t*)&b;
    return r;
}

__global__ void __launch_bounds__(256) k_gather_h(
    const uint2* __restrict__ src, uint2* __restrict__ dst,
    const int* __restrict__ rowptr, const int* __restrict__ esrc,
    const float* __restrict__ enorm, const float* __restrict__ dinv,
    float* __restrict__ osum, float* __restrict__ osumsq)
{
    __shared__ float sbs[128], sbq[128];
    int gy = blockIdx.y;
    src += (size_t)gy * NN * 32;        // row = 32 uint2 (128 half)
    dst += (size_t)gy * NN * 32;
    int tid = threadIdx.x, wid = tid >> 5, lane = tid & 31;
    if (tid < 128) { sbs[tid] = 0.f; sbq[tid] = 0.f; }
    __syncthreads();

    float s[4] = {0.f, 0.f, 0.f, 0.f}, q[4] = {0.f, 0.f, 0.f, 0.f};
    int n0 = blockIdx.x * 64 + wid * 8;
    for (int i = 0; i < 8; ++i) {
        int n = n0 + i;
        if (n >= NN) break;
        float dw = dinv[n];
        float w0 = dw * dw;
        float4 a = h2f4(src[(size_t)n * 32 + lane]);
        float4 acc = make_float4(a.x * w0, a.y * w0, a.z * w0, a.w * w0);
        int j0 = rowptr[n], j1 = rowptr[n + 1];
        int j = j0;
        for (; j + 8 <= j1; j += 8) {
            uint2 rv[8];
            float u[8];
            #pragma unroll
            for (int t = 0; t < 8; ++t) {
                rv[t] = src[(size_t)esrc[j+t] * 32 + lane];
                u[t]  = enorm[j+t];
            }
            #pragma unroll
            for (int t = 0; t < 8; ++t) {
                float4 v = h2f4(rv[t]);
                acc.x += u[t]*v.x; acc.y += u[t]*v.y;
                acc.z += u[t]*v.z; acc.w += u[t]*v.w;
            }
        }
        for (; j + 4 <= j1; j += 4) {
            uint2 rv[4];
            float u[4];
            #pragma unroll
            for (int t = 0; t < 4; ++t) {
                rv[t] = src[(size_t)esrc[j+t] * 32 + lane];
                u[t]  = enorm[j+t];
            }
            #pragma unroll
            for (int t = 0; t < 4; ++t) {
                float4 v = h2f4(rv[t]);
                acc.x += u[t]*v.x; acc.y += u[t]*v.y;
                acc.z += u[t]*v.z; acc.w += u[t]*v.w;
            }
        }
        for (; j < j1; ++j) {
            float w = enorm[j];
            float4 v = h2f4(src[(size_t)esrc[j] * 32 + lane]);
            acc.x += w * v.x; acc.y += w * v.y; acc.z += w * v.z; acc.w += w * v.w;
        }
        dst[(size_t)n * 32 + lane] = f4h2(acc);
        s[0] += acc.x; q[0] += acc.x * acc.x;
        s[1] += acc.y; q[1] += acc.y * acc.y;
        s[2] += acc.z; q[2] += acc.z * acc.z;
        s[3] += acc.w; q[3] += acc.w * acc.w;
    }
    int c = lane * 4;
    atomicAdd(&sbs[c + 0], s[0]); atomicAdd(&sbq[c + 0], q[0]);
    atomicAdd(&sbs[c + 1], s[1]); atomicAdd(&sbq[c + 1], q[1]);
    atomicAdd(&sbs[c + 2], s[2]); atomicAdd(&sbq[c + 2], q[2]);
    atomicAdd(&sbs[c + 3], s[3]); atomicAdd(&sbq[c + 3], q[3]);
    __syncthreads();
    if (tid < 128) {
        atomicAdd(&osum[gy * DD + tid], sbs[tid]);
        atomicAdd(&osumsq[gy * DD + tid], sbq[tid]);
    }
}

// ---------------- GEMM: C = A @ W^T, mma.sync fp16 2-term weight split ----------------
// Warp tiling: 8 warps as 4 row-groups x 2 col-groups; warp = 32 rows x 64 cols.
// smem: WH | WL | A, each 128 rows x 136 fp16 (272B row stride)
#define TROW 272
#define SM_WH 0
#define SM_WL (SM_WH + 128 * TROW)
#define SM_A  (SM_WL + 128 * TROW)
#define GT_SMEM (SM_A + 128 * TROW)

__device__ __forceinline__ void mma_f16(float* d, const uint32_t* a, const uint32_t* b) {
    asm volatile(
        "mma.sync.aligned.m16n8k16.row.col.f32.f16.f16.f32 "
        "{%0,%1,%2,%3}, {%4,%5,%6,%7}, {%8,%9}, {%0,%1,%2,%3};"
        : "+f"(d[0]), "+f"(d[1]), "+f"(d[2]), "+f"(d[3])
        : "r"(a[0]), "r"(a[1]), "r"(a[2]), "r"(a[3]), "r"(b[0]), "r"(b[1]));
}

// A input: fp32 (Af) or fp16 (Ah16) — exactly one non-null. Output: fp16 (Ch).
__global__ void __launch_bounds__(256) k_gemm_mma(
    const float* __restrict__ Af, const __half* __restrict__ Ah16,
    const __half* __restrict__ Bh, const __half* __restrict__ Bl,
    __half* __restrict__ Ch, int M,
    const float* __restrict__ bn_sum, const float* __restrict__ bn_sumsq,
    const float* __restrict__ gamma, const float* __restrict__ beta,
    const float* __restrict__ alpha_p, int applyBN,
    float* osum, float* osumsq, int wantStats, size_t aStride)
{
    extern __shared__ char sm[];
    __shared__ float sbs[128], sbq[128];
    __shared__ float sScale[128], sShift[128];
    int gy = blockIdx.y;
    if (Af)   Af   += (size_t)gy * aStride;
    if (Ah16) Ah16 += (size_t)gy * aStride;
    Bh += (size_t)gy * (DD * DD);
    Bl += (size_t)gy * (DD * DD);
    Ch += (size_t)gy * NN * DD;
    if (applyBN) {
        bn_sum += gy * DD; bn_sumsq += gy * DD;
        gamma  += gy * DD; beta     += gy * DD;
    }
    int tid = threadIdx.x, wid = tid >> 5, lane = tid & 31;

    if (wantStats && tid < 128) { sbs[tid] = 0.f; sbq[tid] = 0.f; }

    // --- precompute BN affine per column (scale = rs*gamma, shift = beta - mu*scale) ---
    float alpha = 0.f;
    if (applyBN) {
        alpha = *alpha_p;
        if (tid < 128) {
            const float invN = 1.0f / (float)NN;
            float mu  = bn_sum[tid] * invN;
            float var = bn_sumsq[tid] * invN - mu * mu;
            float rs  = rsqrtf(var + BN_EPS);
            float sc  = rs * gamma[tid];
            sScale[tid] = sc;
            sShift[tid] = beta[tid] - mu * sc;
        }
        __syncthreads();
    }

    // --- load W tiles (fp16 hi + residual, [n][k]) ---
    {
        int n = tid >> 1;
        int k0 = (tid & 1) * 64;
        const uint4* bh = (const uint4*)(Bh + (size_t)n * 128 + k0);
        const uint4* bl = (const uint4*)(Bl + (size_t)n * 128 + k0);
        char* wh = sm + SM_WH + n * TROW + k0 * 2;
        char* wl = sm + SM_WL + n * TROW + k0 * 2;
        #pragma unroll
        for (int i = 0; i < 8; ++i) {
            *(uint4*)(wh + i * 16) = bh[i];
            *(uint4*)(wl + i * 16) = bl[i];
        }
    }
    // --- load A rows, optional fused BN+PReLU (affine form), round to fp16 in smem ---
    {
        int r = tid >> 1;
        int k0 = (tid & 1) * 64;
        int gr = blockIdx.x * 128 + r;
        bool valid = gr < M;
        char* ap = sm + SM_A + r * TROW + k0 * 2;
        #pragma unroll
        for (int i = 0; i < 16; ++i) {
            int k = k0 + i * 4;
            float v[4] = {0.f, 0.f, 0.f, 0.f};
            if (valid) {
                if (Ah16) {
                    uint2 hv = *(const uint2*)(Ah16 + (size_t)gr * 128 + k);
                    __half2* hh = (__half2*)&hv;
                    float2 f0 = __half22float2(hh[0]), f1 = __half22float2(hh[1]);
                    v[0] = f0.x; v[1] = f0.y; v[2] = f1.x; v[3] = f1.y;
                } else {
                    float4 f = *(const float4*)(Af + (size_t)gr * 128 + k);
                    v[0] = f.x; v[1] = f.y; v[2] = f.z; v[3] = f.w;
                }
            }
            if (applyBN) {
                #pragma unroll
                for (int j = 0; j < 4; ++j) {
                    float z = v[j] * sScale[k + j] + sShift[k + j];
                    v[j] = (z > 0.f) ? z : alpha * z;
                }
            }
            __half2 p0 = __floats2half2_rn(v[0], v[1]);
            __half2 p1 = __floats2half2_rn(v[2], v[3]);
            *(uint2*)(ap + i * 8) = make_uint2(*(uint32_t*)&p0, *(uint32_t*)&p1);
        }
    }
    __syncthreads();

    // --- warp MMA: warp (rg, cg) owns rows [rg*32, +32), cols [cg*64, +64) ---
    int rg = wid >> 1, cg = wid & 1;
    float acc[2][8][4];
    #pragma unroll
    for (int rt = 0; rt < 2; ++rt)
        #pragma unroll
        for (int nt = 0; nt < 8; ++nt)
            #pragma unroll
            for (int qq = 0; qq < 4; ++qq) acc[rt][nt][qq] = 0.f;

    int qrow = lane >> 2;
    int kb   = (lane & 3) * 4;

    #pragma unroll
    for (int kk = 0; kk < 8; ++kk) {
        int kbyte = kk * 32 + kb;
        uint32_t a_[2][4];
        #pragma unroll
        for (int rt = 0; rt < 2; ++rt) {
            const char* arow = sm + SM_A + (rg * 32 + rt * 16 + qrow) * TROW + kbyte;
            a_[rt][0] = *(const uint32_t*)(arow);
            a_[rt][1] = *(const uint32_t*)(arow + 8 * TROW);
            a_[rt][2] = *(const uint32_t*)(arow + 16);
            a_[rt][3] = *(const uint32_t*)(arow + 8 * TROW + 16);
        }
        #pragma unroll
        for (int nt = 0; nt < 8; ++nt) {
            int ncol = cg * 64 + nt * 8;
            const char* brow  = sm + SM_WH + (ncol + qrow) * TROW + kbyte;
            const char* browl = sm + SM_WL + (ncol + qrow) * TROW + kbyte;
            uint32_t b_h[2], b_l[2];
            b_h[0] = *(const uint32_t*)(brow);
            b_h[1] = *(const uint32_t*)(brow + 16);
            b_l[0] = *(const uint32_t*)(browl);
            b_l[1] = *(const uint32_t*)(browl + 16);
            #pragma unroll
            for (int rt = 0; rt < 2; ++rt) {
                mma_f16(acc[rt][nt], a_[rt], b_h);
                mma_f16(acc[rt][nt], a_[rt], b_l);
            }
        }
    }

    // --- epilogue: store fp16 + optional fused BN stats ---
    int colb = (lane & 3) * 2;
    #pragma unroll
    for (int rt = 0; rt < 2; ++rt) {
        int row0 = blockIdx.x * 128 + rg * 32 + rt * 16 + qrow;
        int row1 = row0 + 8;
        #pragma unroll
        for (int nt = 0; nt < 8; ++nt) {
            int col = cg * 64 + nt * 8 + colb;
            if (row0 < M) *(__half2*)(Ch + (size_t)row0 * 128 + col) = __floats2half2_rn(acc[rt][nt][0], acc[rt][nt][1]);
            if (row1 < M) *(__half2*)(Ch + (size_t)row1 * 128 + col) = __floats2half2_rn(acc[rt][nt][2], acc[rt][nt][3]);
        }
    }
    if (wantStats) {
        #pragma unroll
        for (int nt = 0; nt < 8; ++nt) {
            float s0 = acc[0][nt][0] + acc[0][nt][2] + acc[1][nt][0] + acc[1][nt][2];
            float s1 = acc[0][nt][1] + acc[0][nt][3] + acc[1][nt][1] + acc[1][nt][3];
            float q0 = acc[0][nt][0]*acc[0][nt][0] + acc[0][nt][2]*acc[0][nt][2]
                     + acc[1][nt][0]*acc[1][nt][0] + acc[1][nt][2]*acc[1][nt][2];
            float q1 = acc[0][nt][1]*acc[0][nt][1] + acc[0][nt][3]*acc[0][nt][3]
                     + acc[1][nt][1]*acc[1][nt][1] + acc[1][nt][3]*acc[1][nt][3];
            #pragma unroll
            for (int o = 4; o < 32; o <<= 1) {
                s0 += __shfl_xor_sync(0xffffffffu, s0, o);
                s1 += __shfl_xor_sync(0xffffffffu, s1, o);
                q0 += __shfl_xor_sync(0xffffffffu, q0, o);
                q1 += __shfl_xor_sync(0xffffffffu, q1, o);
            }
            if (lane < 4) {
                int c0 = cg * 64 + nt * 8 + lane * 2;
                atomicAdd(&sbs[c0],     s0); atomicAdd(&sbq[c0],     q0);
                atomicAdd(&sbs[c0 + 1], s1); atomicAdd(&sbq[c0 + 1], q1);
            }
        }
        __syncthreads();
        if (tid < 128) {
            atomicAdd(&osum[gy * DD + tid], sbs[tid]);
            atomicAdd(&osumsq[gy * DD + tid], sbq[tid]);
        }
    }
}

// ---------------- final: BN2 + PReLU + mixture, shared affine table ----------------
__global__ void __launch_bounds__(256) k_final(
    const __half2* __restrict__ t2,
    const float* __restrict__ s2, const float* __restrict__ q2,
    const float* __restrict__ gamma2, const float* __restrict__ beta2,
    const float* __restrict__ alpha_p,
    const float* __restrict__ mix, float2* __restrict__ out)
{
    __shared__ float sc[GG * DD], sh[GG * DD];
    int tid = threadIdx.x;
    const float invN = 1.0f / (float)NN;
    #pragma unroll
    for (int r = 0; r < 2; ++r) {
        int c = tid + r * 256;
        float mu  = s2[c] * invN;
        float var = q2[c] * invN - mu * mu;
        float rs  = rsqrtf(var + BN_EPS);
        float scale = rs * gamma2[c];
        sc[c] = scale;
        sh[c] = beta2[c] - mu * scale;
    }
    __syncthreads();

    int idx = blockIdx.x * blockDim.x + tid;     // over NN*DD/2 half2
    if (idx >= NN * DD / 2) return;
    int n = idx >> 6;
    int c = (idx & 63) * 2;
    float a = *alpha_p;
    float r0 = 0.f, r1 = 0.f;
    #pragma unroll
    for (int g = 0; g < GG; ++g) {
        float2 t = __half22float2(t2[(size_t)g * (NN * DD / 2) + idx]);
        float v0 = t.x * sc[g * DD + c]     + sh[g * DD + c];
        float v1 = t.y * sc[g * DD + c + 1] + sh[g * DD + c + 1];
        v0 = (v0 > 0.f) ? v0 : a * v0;
        v1 = (v1 > 0.f) ? v1 : a * v1;
        float m = mix[(size_t)n * GG + g];
        r0 += m * v0;
        r1 += m * v1;
    }
    out[idx] = make_float2(r0, r1);
}

// ---------------- launch ----------------
extern "C" void kernel_launch(void* const* d_in, const int* in_sizes, int n_in,
                              void* d_out, int out_size) {
    const float* x      = (const float*)d_in[0];
    const int*   ei     = (const int*)d_in[1];
    const float* W1     = (const float*)d_in[2];
    const float* W2     = (const float*)d_in[4];
    const float* gamma1 = (const float*)d_in[6];
    const float* beta1  = (const float*)d_in[7];
    const float* gamma2 = (const float*)d_in[8];
    const float* beta2  = (const float*)d_in[9];
    const float* alpha  = (const float*)d_in[10];
    const float* mixe   = (const float*)d_in[11];
    float*       out    = (float*)d_out;

    void* p;
    cudaGetSymbolAddress(&p, g_cnt);    int* cnt    = (int*)p;
    cudaGetSymbolAddress(&p, g_rowptr); int* rowptr = (int*)p;
    cudaGetSymbolAddress(&p, g_cursor); int* cursor = (int*)p;
    cudaGetSymbolAddress(&p, g_bsum);   int* bsum   = (int*)p;
    cudaGetSymbolAddress(&p, g_esrc);   int* esrc   = (int*)p;
    cudaGetSymbolAddress(&p, g_enorm);  float* enorm= (float*)p;
    cudaGetSymbolAddress(&p, g_dinv);   float* dinv = (float*)p;
    cudaGetSymbolAddress(&p, g_xa);     float* xa   = (float*)p;
    cudaGetSymbolAddress(&p, g_z1);     __half* z1  = (__half*)p;
    cudaGetSymbolAddress(&p, g_h2);     __half* h2  = (__half*)p;
    cudaGetSymbolAddress(&p, g_t2);     __half* t2  = (__half*)p;
    cudaGetSymbolAddress(&p, g_mix);    float* mix  = (float*)p;
    cudaGetSymbolAddress(&p, g_s1);     float* s1   = (float*)p;
    cudaGetSymbolAddress(&p, g_q1);     float* q1   = (float*)p;
    cudaGetSymbolAddress(&p, g_s2);     float* s2   = (float*)p;
    cudaGetSymbolAddress(&p, g_q2);     float* q2   = (float*)p;
    cudaGetSymbolAddress(&p, g_w1h);    __half* w1h = (__half*)p;
    cudaGetSymbolAddress(&p, g_w1l);    __half* w1l = (__half*)p;
    cudaGetSymbolAddress(&p, g_w2h);    __half* w2h = (__half*)p;
    cudaGetSymbolAddress(&p, g_w2l);    __half* w2l = (__half*)p;

    const int* row = ei;
    const int* col = ei + EE;

    const int T = 256;
    const int gN    = (NN + T) / T;
    const int gE    = (EE + T - 1) / T;
    const int gHM   = (EE + NN + 2 * GG * DD * DD + T - 1) / T;
    const int gFin  = (NN * DD / 2 + T - 1) / T;
    const int gRow  = (NN + 127) / 128;                    // 391
    const int nScan = (NN + 1 + 511) / 512;                // 98
    const int gGath = (NN + 63) / 64;                      // 782

    cudaFuncSetAttribute(k_gemm_mma, cudaFuncAttributeMaxDynamicSharedMemorySize, GT_SMEM);

    // setup: CSR + norm + softmax + weight split (recomputed per call)
    k_zero<<<gN, T>>>(cnt, s1, q1, s2, q2);
    k_hist_misc<<<gHM, T>>>(col, cnt, mixe, mix, W1, w1h, w1l, W2, w2h, w2l);
    k_scan1<<<nScan, 512>>>(cnt, rowptr, bsum, dinv);
    k_scan3<<<nScan, 512>>>(rowptr, bsum, cursor, nScan);
    k_place<<<gE, T>>>(row, col, dinv, cursor, esrc, enorm);

    // shared layer-1 propagate: xa = P @ x (fp32)
    k_gather<<<gGath, T>>>((const float4*)x, (float4*)xa, rowptr, esrc, enorm, dinv);

    // layer 1 (all G): z1[g] = xa @ W1[g]^T (fp16 out), fused stats (fp32) -> s1/q1
    k_gemm_mma<<<dim3(gRow, GG), T, GT_SMEM>>>(
        xa, nullptr, w1h, w1l, z1, NN,
        nullptr, nullptr, nullptr, nullptr, nullptr, 0,
        s1, q1, 1, 0 /* shared A */);

    // layer 2 (all G): h2[g] = prelu(BN(z1[g])) @ W2[g]^T (fp16 in/out), BN affine fused
    k_gemm_mma<<<dim3(gRow, GG), T, GT_SMEM>>>(
        nullptr, z1, w2h, w2l, h2, NN,
        s1, q1, gamma1, beta1, alpha, 1,
        nullptr, nullptr, 0, (size_t)NN * DD);

    // propagate (all G): t2[g] = P @ h2[g] (fp16 in/out, fp32 acc), fused stats -> s2/q2
    k_gather_h<<<dim3(gGath, GG), T>>>((const uint2*)h2, (uint2*)t2,
                                       rowptr, esrc, enorm, dinv, s2, q2);

    // final: BN2 + PReLU + softmax-mix, shared affine table, single pass
    k_final<<<gFin, T>>>((const __half2*)t2, s2, q2, gamma2, beta2, alpha, mix, (float2*)out);
}